// round 3
// baseline (speedup 1.0000x reference)
#include <cuda_runtime.h>

#define Bc 2
#define Sc 2048
#define Dc 1024
#define Hc 16
#define HDc 64
#define Mc (Bc*Sc)

typedef unsigned long long u64;

__device__ __forceinline__ u64 pk2(float x, float y) {
    u64 r; asm("mov.b64 %0, {%1, %2};" : "=l"(r) : "f"(x), "f"(y)); return r;
}
__device__ __forceinline__ void fma2(u64& d, u64 a, u64 b) {
    asm("fma.rn.f32x2 %0, %1, %2, %0;" : "+l"(d) : "l"(a), "l"(b));
}
__device__ __forceinline__ float2 up2(u64 v) {
    float2 f; asm("mov.b64 {%0, %1}, %2;" : "=f"(f.x), "=f"(f.y) : "l"(v)); return f;
}

// Scratch (static device globals; no runtime allocation)
__device__ float g_q[(size_t)Mc * Dc];
__device__ float g_k[(size_t)Mc * Dc];
__device__ float g_v[(size_t)Mc * Dc];
__device__ float g_ao[(size_t)Mc * Dc];
__device__ float g_m[Mc * Hc];
__device__ float g_l[Mc * Hc];

// C[m][n] = sum_k A[m][k] * Bm[n][k]   (A: MxK row-major, Bm: NxK row-major)
__global__ __launch_bounds__(256) void sgemm_nt(const float* __restrict__ A,
                                                const float* __restrict__ Bm,
                                                float* __restrict__ C,
                                                int M, int N, int K) {
    __shared__ float As[16][132];
    __shared__ float Bs[16][132];
    int t = threadIdx.x;
    int tx = t & 15, ty = t >> 4;
    int brow = blockIdx.y * 128, bcol = blockIdx.x * 128;
    u64 acc[8][4];
#pragma unroll
    for (int i = 0; i < 8; i++)
#pragma unroll
        for (int j = 0; j < 4; j++) acc[i][j] = 0ULL;

    for (int k0 = 0; k0 < K; k0 += 16) {
#pragma unroll
        for (int l = 0; l < 2; l++) {
            int lin = t + l * 256;          // 0..511
            int r = lin >> 2;               // 0..127
            int c = (lin & 3) * 4;          // 0,4,8,12
            float4 va = *reinterpret_cast<const float4*>(A + (size_t)(brow + r) * K + k0 + c);
            As[c + 0][r] = va.x; As[c + 1][r] = va.y; As[c + 2][r] = va.z; As[c + 3][r] = va.w;
            float4 vb = *reinterpret_cast<const float4*>(Bm + (size_t)(bcol + r) * K + k0 + c);
            Bs[c + 0][r] = vb.x; Bs[c + 1][r] = vb.y; Bs[c + 2][r] = vb.z; Bs[c + 3][r] = vb.w;
        }
        __syncthreads();
#pragma unroll
        for (int kk = 0; kk < 16; kk++) {
            float4 a0 = *reinterpret_cast<float4*>(&As[kk][ty * 8]);
            float4 a1 = *reinterpret_cast<float4*>(&As[kk][ty * 8 + 4]);
            float4 b0 = *reinterpret_cast<float4*>(&Bs[kk][tx * 8]);
            float4 b1 = *reinterpret_cast<float4*>(&Bs[kk][tx * 8 + 4]);
            u64 bp[4];
            bp[0] = pk2(b0.x, b0.y); bp[1] = pk2(b0.z, b0.w);
            bp[2] = pk2(b1.x, b1.y); bp[3] = pk2(b1.z, b1.w);
            float a[8] = {a0.x, a0.y, a0.z, a0.w, a1.x, a1.y, a1.z, a1.w};
#pragma unroll
            for (int i = 0; i < 8; i++) {
                u64 ad = pk2(a[i], a[i]);
#pragma unroll
                for (int j = 0; j < 4; j++)
                    fma2(acc[i][j], ad, bp[j]);
            }
        }
        __syncthreads();
    }
#pragma unroll
    for (int i = 0; i < 8; i++) {
        float* cp = C + (size_t)(brow + ty * 8 + i) * N + bcol + tx * 8;
        float2 c0 = up2(acc[i][0]), c1 = up2(acc[i][1]);
        float2 c2 = up2(acc[i][2]), c3 = up2(acc[i][3]);
        *reinterpret_cast<float4*>(cp)     = make_float4(c0.x, c0.y, c1.x, c1.y);
        *reinterpret_cast<float4*>(cp + 4) = make_float4(c2.x, c2.y, c3.x, c3.y);
    }
}

// In-place RoPE on g_q (blockIdx.y==0) / g_k (blockIdx.y==1)
__global__ __launch_bounds__(256) void rope_kernel(const float* __restrict__ cosb,
                                                   const float* __restrict__ sinb) {
    int tid = blockIdx.x * 256 + threadIdx.x;   // pair index
    int i = tid & 31;
    int h = (tid >> 5) & 15;
    int s = (tid >> 9) & 2047;
    int b = tid >> 20;
    float* p = blockIdx.y ? g_k : g_q;
    size_t off = ((size_t)(b * Sc + s)) * Dc + h * HDc + 2 * i;
    float2 t2 = *reinterpret_cast<float2*>(p + off);
    float c = cosb[s * 32 + i], sn = sinb[s * 32 + i];
    *reinterpret_cast<float2*>(p + off) = make_float2(t2.x * c - t2.y * sn,
                                                      t2.x * sn + t2.y * c);
}

// Pass 1: raw scaled scores -> attn buffer (scratch), online row max & sumexp -> g_m/g_l
__global__ __launch_bounds__(256) void attn_scores(float* __restrict__ attn) {
    __shared__ float Qs[64][68];   // [dd][i]
    __shared__ float Ks[64][68];   // [dd][j]
    int t = threadIdx.x;
    int tx = t & 15, ty = t >> 4;
    int bh = blockIdx.y;
    int b = bh >> 4, h = bh & 15;
    int i0 = blockIdx.x * 64;

    const float* qb = g_q + ((size_t)(b * Sc + i0)) * Dc + h * HDc;
#pragma unroll
    for (int l = 0; l < 4; l++) {
        int lin = t + l * 256;
        int r = lin >> 4;
        int c = (lin & 15) * 4;
        float4 v = *reinterpret_cast<const float4*>(qb + (size_t)r * Dc + c);
        Qs[c + 0][r] = v.x; Qs[c + 1][r] = v.y; Qs[c + 2][r] = v.z; Qs[c + 3][r] = v.w;
    }
    float m[4], l_[4];
#pragma unroll
    for (int r = 0; r < 4; r++) { m[r] = __int_as_float(0xff800000u); l_[r] = 0.f; }

    for (int jt = 0; jt < 32; jt++) {
        int j0 = jt * 64;
        const float* kb = g_k + ((size_t)(b * Sc + j0)) * Dc + h * HDc;
        __syncthreads();
#pragma unroll
        for (int l = 0; l < 4; l++) {
            int lin = t + l * 256;
            int r = lin >> 4;
            int c = (lin & 15) * 4;
            float4 v = *reinterpret_cast<const float4*>(kb + (size_t)r * Dc + c);
            Ks[c + 0][r] = v.x; Ks[c + 1][r] = v.y; Ks[c + 2][r] = v.z; Ks[c + 3][r] = v.w;
        }
        __syncthreads();

        u64 s2[4][2];
#pragma unroll
        for (int i = 0; i < 4; i++) { s2[i][0] = 0ULL; s2[i][1] = 0ULL; }

#pragma unroll 16
        for (int kk = 0; kk < 64; kk++) {
            float4 av = *reinterpret_cast<float4*>(&Qs[kk][ty * 4]);
            float4 bv = *reinterpret_cast<float4*>(&Ks[kk][tx * 4]);
            u64 bp0 = pk2(bv.x, bv.y), bp1 = pk2(bv.z, bv.w);
            float a[4] = {av.x, av.y, av.z, av.w};
#pragma unroll
            for (int i = 0; i < 4; i++) {
                u64 ad = pk2(a[i], a[i]);
                fma2(s2[i][0], ad, bp0);
                fma2(s2[i][1], ad, bp1);
            }
        }

#pragma unroll
        for (int r = 0; r < 4; r++) {
            float2 sa = up2(s2[r][0]), sb = up2(s2[r][1]);
            float s0 = sa.x * 0.125f, s1 = sa.y * 0.125f;
            float sx = sb.x * 0.125f, s3 = sb.y * 0.125f;
            float rmax = fmaxf(fmaxf(s0, s1), fmaxf(sx, s3));
#pragma unroll
            for (int o = 8; o > 0; o >>= 1)
                rmax = fmaxf(rmax, __shfl_xor_sync(0xffffffffu, rmax, o, 16));
            float mn = fmaxf(m[r], rmax);
            float corr = __expf(m[r] - mn);
            float ps = __expf(s0 - mn) + __expf(s1 - mn) +
                       __expf(sx - mn) + __expf(s3 - mn);
#pragma unroll
            for (int o = 8; o > 0; o >>= 1)
                ps += __shfl_xor_sync(0xffffffffu, ps, o, 16);
            l_[r] = l_[r] * corr + ps;
            m[r] = mn;
            size_t off = ((size_t)((b * Sc + i0 + ty * 4 + r) * Hc + h)) * Sc + j0 + tx * 4;
            *reinterpret_cast<float4*>(attn + off) = make_float4(s0, s1, sx, s3);
        }
    }
    if (tx == 0) {
#pragma unroll
        for (int r = 0; r < 4; r++) {
            int idx = (b * Sc + i0 + ty * 4 + r) * Hc + h;
            g_m[idx] = m[r];
            g_l[idx] = l_[r];
        }
    }
}

// Pass 2: normalize weights (final output), entropy, o = w @ V
__global__ __launch_bounds__(256) void attn_av(float* __restrict__ attn, float* __restrict__ ent) {
    __shared__ float Ws[64][68];   // [j][i]
    __shared__ float Vs[64][68];   // [j][c]
    int t = threadIdx.x;
    int tx = t & 15, ty = t >> 4;
    int bh = blockIdx.y;
    int b = bh >> 4, h = bh & 15;
    int i0 = blockIdx.x * 64;

    float m[4], linv[4], entacc[4] = {0.f, 0.f, 0.f, 0.f};
#pragma unroll
    for (int r = 0; r < 4; r++) {
        int idx = (b * Sc + i0 + ty * 4 + r) * Hc + h;
        m[r] = g_m[idx];
        linv[r] = 1.f / g_l[idx];
    }
    u64 o2[4][2];
#pragma unroll
    for (int i = 0; i < 4; i++) { o2[i][0] = 0ULL; o2[i][1] = 0ULL; }

    for (int jt = 0; jt < 32; jt++) {
        int j0 = jt * 64;
        __syncthreads();
#pragma unroll
        for (int r = 0; r < 4; r++) {
            size_t off = ((size_t)((b * Sc + i0 + ty * 4 + r) * Hc + h)) * Sc + j0 + tx * 4;
            float4 sv = *reinterpret_cast<const float4*>(attn + off);
            float4 w;
            w.x = __expf(sv.x - m[r]) * linv[r];
            w.y = __expf(sv.y - m[r]) * linv[r];
            w.z = __expf(sv.z - m[r]) * linv[r];
            w.w = __expf(sv.w - m[r]) * linv[r];
            entacc[r] += w.x * __log2f(w.x + 1e-9f) + w.y * __log2f(w.y + 1e-9f) +
                         w.z * __log2f(w.z + 1e-9f) + w.w * __log2f(w.w + 1e-9f);
            *reinterpret_cast<float4*>(attn + off) = w;
            Ws[tx * 4 + 0][ty * 4 + r] = w.x;
            Ws[tx * 4 + 1][ty * 4 + r] = w.y;
            Ws[tx * 4 + 2][ty * 4 + r] = w.z;
            Ws[tx * 4 + 3][ty * 4 + r] = w.w;
        }
        const float* vb = g_v + ((size_t)(b * Sc + j0)) * Dc + h * HDc;
#pragma unroll
        for (int l = 0; l < 4; l++) {
            int lin = t + l * 256;
            int r = lin >> 4;
            int c = (lin & 15) * 4;
            *reinterpret_cast<float4*>(&Vs[r][c]) =
                *reinterpret_cast<const float4*>(vb + (size_t)r * Dc + c);
        }
        __syncthreads();
#pragma unroll 16
        for (int jj = 0; jj < 64; jj++) {
            float4 av = *reinterpret_cast<float4*>(&Ws[jj][ty * 4]);
            float4 bv = *reinterpret_cast<float4*>(&Vs[jj][tx * 4]);
            u64 bp0 = pk2(bv.x, bv.y), bp1 = pk2(bv.z, bv.w);
            float a[4] = {av.x, av.y, av.z, av.w};
#pragma unroll
            for (int i = 0; i < 4; i++) {
                u64 ad = pk2(a[i], a[i]);
                fma2(o2[i][0], ad, bp0);
                fma2(o2[i][1], ad, bp1);
            }
        }
    }
#pragma unroll
    for (int r = 0; r < 4; r++) {
        float* op = g_ao + ((size_t)(b * Sc + i0 + ty * 4 + r)) * Dc + h * HDc + tx * 4;
        float2 c0 = up2(o2[r][0]), c1 = up2(o2[r][1]);
        *reinterpret_cast<float4*>(op) = make_float4(c0.x, c0.y, c1.x, c1.y);
    }
#pragma unroll
    for (int r = 0; r < 4; r++) {
        float e = entacc[r];
#pragma unroll
        for (int oo = 8; oo > 0; oo >>= 1)
            e += __shfl_xor_sync(0xffffffffu, e, oo, 16);
        if (tx == 0) ent[(b * Sc + i0 + ty * 4 + r) * Hc + h] = -e;
    }
}

extern "C" void kernel_launch(void* const* d_in, const int* in_sizes, int n_in,
                              void* d_out, int out_size) {
    (void)in_sizes; (void)n_in; (void)out_size;
    const float* x    = (const float*)d_in[0];
    const float* cosb = (const float*)d_in[1];
    const float* sinb = (const float*)d_in[2];
    const float* wq   = (const float*)d_in[3];
    const float* wk   = (const float*)d_in[4];
    const float* wv   = (const float*)d_in[5];
    const float* wo   = (const float*)d_in[6];

    float* out  = (float*)d_out;                       // (B,S,D)
    float* attn = out + (size_t)Mc * Dc;               // (B,S,H,S)
    float* ent  = attn + (size_t)Mc * Hc * (size_t)Sc; // (B,S,H)

    float *q, *k, *v, *ao;
    cudaGetSymbolAddress((void**)&q,  g_q);
    cudaGetSymbolAddress((void**)&k,  g_k);
    cudaGetSymbolAddress((void**)&v,  g_v);
    cudaGetSymbolAddress((void**)&ao, g_ao);

    dim3 gproj(Dc / 128, Mc / 128);
    sgemm_nt<<<gproj, 256>>>(x, wq, q, Mc, Dc, Dc);
    sgemm_nt<<<gproj, 256>>>(x, wk, k, Mc, Dc, Dc);
    sgemm_nt<<<gproj, 256>>>(x, wv, v, Mc, Dc, Dc);
    rope_kernel<<<dim3((Bc * Sc * Hc * 32) / 256, 2), 256>>>(cosb, sinb);
    attn_scores<<<dim3(Sc / 64, Bc * Hc), 256>>>(attn);
    attn_av<<<dim3(Sc / 64, Bc * Hc), 256>>>(attn, ent);
    sgemm_nt<<<gproj, 256>>>(ao, wo, out, Mc, Dc, Dc);
}

// round 4
// speedup vs baseline: 1.0487x; 1.0487x over previous
#include <cuda_runtime.h>
#include <cuda_bf16.h>

#define Bc 2
#define Sc 2048
#define Dc 1024
#define Hc 16
#define Mc (Bc*Sc)

typedef unsigned u32;
typedef __nv_bfloat16 bf16;

__device__ bf16 g_xh[(size_t)Mc*Dc], g_xl[(size_t)Mc*Dc];
__device__ bf16 g_wh[4*Dc*Dc], g_wl[4*Dc*Dc];
__device__ bf16 g_qh[(size_t)Mc*Dc], g_ql[(size_t)Mc*Dc];
__device__ bf16 g_kh[(size_t)Mc*Dc], g_kl[(size_t)Mc*Dc];
__device__ bf16 g_vth[(size_t)Bc*Dc*Sc], g_vtl[(size_t)Bc*Dc*Sc];
__device__ bf16 g_aoh[(size_t)Mc*Dc], g_aol[(size_t)Mc*Dc];
__device__ float g_q[(size_t)Mc*Dc], g_k[(size_t)Mc*Dc], g_v[(size_t)Mc*Dc], g_ao[(size_t)Mc*Dc];
__device__ float g_m[Mc*Hc], g_l[Mc*Hc];

__device__ __forceinline__ void mma16816(float* c, const u32* a, const u32* b) {
    asm volatile("mma.sync.aligned.m16n8k16.row.col.f32.bf16.bf16.f32 "
        "{%0,%1,%2,%3},{%4,%5,%6,%7},{%8,%9},{%0,%1,%2,%3};"
        : "+f"(c[0]), "+f"(c[1]), "+f"(c[2]), "+f"(c[3])
        : "r"(a[0]), "r"(a[1]), "r"(a[2]), "r"(a[3]), "r"(b[0]), "r"(b[1]));
}
__device__ __forceinline__ u32 pkbf(float x, float y) {
    bf16 a = __float2bfloat16(x), b = __float2bfloat16(y);
    return (u32)__bfloat16_as_ushort(a) | ((u32)__bfloat16_as_ushort(b) << 16);
}
__device__ __forceinline__ float bflo(float x) {
    return x - __bfloat162float(__float2bfloat16(x));
}

__global__ __launch_bounds__(256) void cvt_split(const float* __restrict__ in,
                                                 bf16* __restrict__ oh, bf16* __restrict__ ol, int n4) {
    int i = blockIdx.x * 256 + threadIdx.x;
    if (i >= n4) return;
    float4 v = ((const float4*)in)[i];
    ((uint2*)oh)[i] = make_uint2(pkbf(v.x, v.y), pkbf(v.z, v.w));
    ((uint2*)ol)[i] = make_uint2(pkbf(bflo(v.x), bflo(v.y)), pkbf(bflo(v.z), bflo(v.w)));
}

__global__ __launch_bounds__(256) void vtrans() {
    __shared__ float ts[32][33];
    int tx = threadIdx.x & 31, ty = threadIdx.x >> 5;
    int s0 = blockIdx.x * 32, d0 = blockIdx.y * 32, b = blockIdx.z;
#pragma unroll
    for (int i = 0; i < 4; i++)
        ts[ty + i * 8][tx] = g_v[((size_t)(b * Sc + s0 + ty + i * 8)) * Dc + d0 + tx];
    __syncthreads();
#pragma unroll
    for (int i = 0; i < 4; i++) {
        int d = ty + i * 8;
        float v = ts[tx][d];
        size_t o = ((size_t)(b * Dc + d0 + d)) * Sc + s0 + tx;
        g_vth[o] = __float2bfloat16(v);
        g_vtl[o] = __float2bfloat16(bflo(v));
    }
}

// C[M=4096, N=1024] = A[4096,1024] * B[1024,1024]^T, 3-term bf16 mma
__global__ __launch_bounds__(256) void gemm_bf3(
    const bf16* __restrict__ Ah, const bf16* __restrict__ Al,
    const bf16* __restrict__ Bh, const bf16* __restrict__ Bl,
    float* __restrict__ C) {
    __shared__ bf16 Ahs[128][40], Als[128][40], Bhs[128][40], Bls[128][40];
    int t = threadIdx.x, lane = t & 31, w = t >> 5;
    int wm = w & 1, wn = w >> 1;
    int g = lane >> 2, c2 = (lane & 3) * 2;
    int brow = blockIdx.y * 128, bcol = blockIdx.x * 128;
    float acc[4][4][4];
#pragma unroll
    for (int a = 0; a < 4; a++)
#pragma unroll
        for (int b2 = 0; b2 < 4; b2++)
#pragma unroll
            for (int q = 0; q < 4; q++) acc[a][b2][q] = 0.f;

    int lr = t >> 1, lc = (t & 1) * 16;
    const bf16* pah = Ah + (size_t)(brow + lr) * Dc + lc;
    const bf16* pal = Al + (size_t)(brow + lr) * Dc + lc;
    const bf16* pbh = Bh + (size_t)(bcol + lr) * Dc + lc;
    const bf16* pbl = Bl + (size_t)(bcol + lr) * Dc + lc;

    for (int k0 = 0; k0 < Dc; k0 += 32) {
        __syncthreads();
        *(uint4*)&Ahs[lr][lc]     = *(const uint4*)(pah + k0);
        *(uint4*)&Ahs[lr][lc + 8] = *(const uint4*)(pah + k0 + 8);
        *(uint4*)&Als[lr][lc]     = *(const uint4*)(pal + k0);
        *(uint4*)&Als[lr][lc + 8] = *(const uint4*)(pal + k0 + 8);
        *(uint4*)&Bhs[lr][lc]     = *(const uint4*)(pbh + k0);
        *(uint4*)&Bhs[lr][lc + 8] = *(const uint4*)(pbh + k0 + 8);
        *(uint4*)&Bls[lr][lc]     = *(const uint4*)(pbl + k0);
        *(uint4*)&Bls[lr][lc + 8] = *(const uint4*)(pbl + k0 + 8);
        __syncthreads();
#pragma unroll
        for (int ks = 0; ks < 32; ks += 16) {
            u32 a_h[4][4], a_l[4][4];
#pragma unroll
            for (int mf = 0; mf < 4; mf++) {
                int ra = wm * 64 + mf * 16 + g;
                a_h[mf][0] = *(const u32*)&Ahs[ra][ks + c2];
                a_h[mf][1] = *(const u32*)&Ahs[ra + 8][ks + c2];
                a_h[mf][2] = *(const u32*)&Ahs[ra][ks + c2 + 8];
                a_h[mf][3] = *(const u32*)&Ahs[ra + 8][ks + c2 + 8];
                a_l[mf][0] = *(const u32*)&Als[ra][ks + c2];
                a_l[mf][1] = *(const u32*)&Als[ra + 8][ks + c2];
                a_l[mf][2] = *(const u32*)&Als[ra][ks + c2 + 8];
                a_l[mf][3] = *(const u32*)&Als[ra + 8][ks + c2 + 8];
            }
#pragma unroll
            for (int nf = 0; nf < 4; nf++) {
                int rb = wn * 32 + nf * 8 + g;
                u32 b_h[2] = { *(const u32*)&Bhs[rb][ks + c2], *(const u32*)&Bhs[rb][ks + c2 + 8] };
                u32 b_l[2] = { *(const u32*)&Bls[rb][ks + c2], *(const u32*)&Bls[rb][ks + c2 + 8] };
#pragma unroll
                for (int mf = 0; mf < 4; mf++) {
                    mma16816(acc[mf][nf], a_h[mf], b_h);
                    mma16816(acc[mf][nf], a_h[mf], b_l);
                    mma16816(acc[mf][nf], a_l[mf], b_h);
                }
            }
        }
    }
#pragma unroll
    for (int mf = 0; mf < 4; mf++)
#pragma unroll
        for (int nf = 0; nf < 4; nf++) {
            int r = brow + wm * 64 + mf * 16 + g;
            int c = bcol + wn * 32 + nf * 8 + c2;
            *(float2*)&C[(size_t)r * Dc + c]       = make_float2(acc[mf][nf][0], acc[mf][nf][1]);
            *(float2*)&C[(size_t)(r + 8) * Dc + c] = make_float2(acc[mf][nf][2], acc[mf][nf][3]);
        }
}

__global__ __launch_bounds__(256) void rope_kernel(const float* __restrict__ cosb,
                                                   const float* __restrict__ sinb) {
    int tid = blockIdx.x * 256 + threadIdx.x;
    int i = tid & 31;
    int h = (tid >> 5) & 15;
    int s = (tid >> 9) & 2047;
    int b = tid >> 20;
    float* p = blockIdx.y ? g_k : g_q;
    size_t off = ((size_t)(b * Sc + s)) * Dc + h * 64 + 2 * i;
    float2 t2 = *reinterpret_cast<float2*>(p + off);
    float c = cosb[s * 32 + i], sn = sinb[s * 32 + i];
    *reinterpret_cast<float2*>(p + off) = make_float2(t2.x * c - t2.y * sn, t2.x * sn + t2.y * c);
}

// Pass 1: scores (mma) -> S scratch, online m/l
__global__ __launch_bounds__(256) void attn1(float* __restrict__ S) {
    int t = threadIdx.x, lane = t & 31, w = t >> 5;
    int g = lane >> 2, c2 = (lane & 3) * 2;
    int b = blockIdx.y >> 4, h = blockIdx.y & 15;
    int i0 = blockIdx.x * 128 + w * 16;
    const bf16* qh = g_qh + ((size_t)(b * Sc + i0 + g)) * Dc + h * 64;
    const bf16* ql = g_ql + ((size_t)(b * Sc + i0 + g)) * Dc + h * 64;
    u32 ah[4][4], al[4][4];
#pragma unroll
    for (int ks = 0; ks < 4; ks++) {
        ah[ks][0] = *(const u32*)(qh + ks * 16 + c2);
        ah[ks][1] = *(const u32*)(qh + 8 * Dc + ks * 16 + c2);
        ah[ks][2] = *(const u32*)(qh + ks * 16 + c2 + 8);
        ah[ks][3] = *(const u32*)(qh + 8 * Dc + ks * 16 + c2 + 8);
        al[ks][0] = *(const u32*)(ql + ks * 16 + c2);
        al[ks][1] = *(const u32*)(ql + 8 * Dc + ks * 16 + c2);
        al[ks][2] = *(const u32*)(ql + ks * 16 + c2 + 8);
        al[ks][3] = *(const u32*)(ql + 8 * Dc + ks * 16 + c2 + 8);
    }
    float m0 = -1e30f, m1 = -1e30f, l0 = 0.f, l1 = 0.f;
    const bf16* kbh = g_kh + ((size_t)b * Sc) * Dc + h * 64;
    const bf16* kbl = g_kl + ((size_t)b * Sc) * Dc + h * 64;
    int idx0 = (b * Sc + i0 + g) * Hc + h;
    size_t srow0 = (size_t)idx0 * Sc;
    size_t srow1 = (size_t)(idx0 + 8 * Hc) * Sc;

    for (int j0 = 0; j0 < Sc; j0 += 16) {
        float sa[2][4];
#pragma unroll
        for (int nt = 0; nt < 2; nt++) {
            float* c = sa[nt];
            c[0] = c[1] = c[2] = c[3] = 0.f;
            const bf16* kh = kbh + (size_t)(j0 + nt * 8 + g) * Dc;
            const bf16* kl = kbl + (size_t)(j0 + nt * 8 + g) * Dc;
#pragma unroll
            for (int ks = 0; ks < 4; ks++) {
                u32 bh2[2] = { *(const u32*)(kh + ks * 16 + c2), *(const u32*)(kh + ks * 16 + c2 + 8) };
                u32 bl2[2] = { *(const u32*)(kl + ks * 16 + c2), *(const u32*)(kl + ks * 16 + c2 + 8) };
                mma16816(c, ah[ks], bh2);
                mma16816(c, ah[ks], bl2);
                mma16816(c, al[ks], bh2);
            }
#pragma unroll
            for (int q = 0; q < 4; q++) c[q] *= 0.125f;
        }
        float mx0 = fmaxf(fmaxf(sa[0][0], sa[0][1]), fmaxf(sa[1][0], sa[1][1]));
        float mx1 = fmaxf(fmaxf(sa[0][2], sa[0][3]), fmaxf(sa[1][2], sa[1][3]));
        float mn0 = fmaxf(m0, mx0), mn1 = fmaxf(m1, mx1);
        l0 = l0 * __expf(m0 - mn0) + __expf(sa[0][0] - mn0) + __expf(sa[0][1] - mn0)
                                   + __expf(sa[1][0] - mn0) + __expf(sa[1][1] - mn0);
        l1 = l1 * __expf(m1 - mn1) + __expf(sa[0][2] - mn1) + __expf(sa[0][3] - mn1)
                                   + __expf(sa[1][2] - mn1) + __expf(sa[1][3] - mn1);
        m0 = mn0; m1 = mn1;
        *(float2*)(S + srow0 + j0 + c2)     = make_float2(sa[0][0], sa[0][1]);
        *(float2*)(S + srow0 + j0 + 8 + c2) = make_float2(sa[1][0], sa[1][1]);
        *(float2*)(S + srow1 + j0 + c2)     = make_float2(sa[0][2], sa[0][3]);
        *(float2*)(S + srow1 + j0 + 8 + c2) = make_float2(sa[1][2], sa[1][3]);
    }
#pragma unroll
    for (int o = 1; o < 4; o <<= 1) {
        float om = __shfl_xor_sync(~0u, m0, o), ol = __shfl_xor_sync(~0u, l0, o);
        float mn = fmaxf(m0, om);
        l0 = l0 * __expf(m0 - mn) + ol * __expf(om - mn); m0 = mn;
        om = __shfl_xor_sync(~0u, m1, o); ol = __shfl_xor_sync(~0u, l1, o);
        mn = fmaxf(m1, om);
        l1 = l1 * __expf(m1 - mn) + ol * __expf(om - mn); m1 = mn;
    }
    if ((lane & 3) == 0) {
        g_m[idx0] = m0; g_l[idx0] = l0;
        g_m[idx0 + 8 * Hc] = m1; g_l[idx0 + 8 * Hc] = l1;
    }
}

// Pass 2: w = exp(s-m)/l -> out, entropy analytic, o = w @ V (mma)
__global__ __launch_bounds__(256) void attn2(float* __restrict__ S, float* __restrict__ ent) {
    int t = threadIdx.x, lane = t & 31, w = t >> 5;
    int g = lane >> 2, c2 = (lane & 3) * 2;
    int b = blockIdx.y >> 4, h = blockIdx.y & 15;
    int i0 = blockIdx.x * 128 + w * 16;
    int idx0 = (b * Sc + i0 + g) * Hc + h;
    float L0 = g_l[idx0], L1 = g_l[idx0 + 8 * Hc];
    float m0 = g_m[idx0], m1 = g_m[idx0 + 8 * Hc];
    float li0 = 1.f / L0, li1 = 1.f / L1;
    size_t srow0 = (size_t)idx0 * Sc;
    size_t srow1 = (size_t)(idx0 + 8 * Hc) * Sc;
    const bf16* vh = g_vth + ((size_t)b * Dc + h * 64) * Sc;
    const bf16* vl = g_vtl + ((size_t)b * Dc + h * 64) * Sc;
    float o[8][4];
#pragma unroll
    for (int n = 0; n < 8; n++)
#pragma unroll
        for (int q = 0; q < 4; q++) o[n][q] = 0.f;
    float ws0 = 0.f, ws1 = 0.f;

    for (int j0 = 0; j0 < Sc; j0 += 16) {
        float2 s01 = *(float2*)(S + srow0 + j0 + c2);
        float2 s23 = *(float2*)(S + srow0 + j0 + 8 + c2);
        float2 s45 = *(float2*)(S + srow1 + j0 + c2);
        float2 s67 = *(float2*)(S + srow1 + j0 + 8 + c2);
        float w0 = __expf(s01.x - m0) * li0, w1 = __expf(s01.y - m0) * li0;
        float w2 = __expf(s23.x - m0) * li0, w3 = __expf(s23.y - m0) * li0;
        float w4 = __expf(s45.x - m1) * li1, w5 = __expf(s45.y - m1) * li1;
        float w6 = __expf(s67.x - m1) * li1, w7 = __expf(s67.y - m1) * li1;
        ws0 += w0 * s01.x + w1 * s01.y + w2 * s23.x + w3 * s23.y;
        ws1 += w4 * s45.x + w5 * s45.y + w6 * s67.x + w7 * s67.y;
        *(float2*)(S + srow0 + j0 + c2)     = make_float2(w0, w1);
        *(float2*)(S + srow0 + j0 + 8 + c2) = make_float2(w2, w3);
        *(float2*)(S + srow1 + j0 + c2)     = make_float2(w4, w5);
        *(float2*)(S + srow1 + j0 + 8 + c2) = make_float2(w6, w7);
        u32 ahg[4] = { pkbf(w0, w1), pkbf(w4, w5), pkbf(w2, w3), pkbf(w6, w7) };
        u32 alg[4] = { pkbf(bflo(w0), bflo(w1)), pkbf(bflo(w4), bflo(w5)),
                       pkbf(bflo(w2), bflo(w3)), pkbf(bflo(w6), bflo(w7)) };
#pragma unroll
        for (int nt = 0; nt < 8; nt++) {
            const bf16* vhp = vh + (size_t)(nt * 8 + g) * Sc + j0;
            const bf16* vlp = vl + (size_t)(nt * 8 + g) * Sc + j0;
            u32 bh2[2] = { *(const u32*)(vhp + c2), *(const u32*)(vhp + c2 + 8) };
            u32 bl2[2] = { *(const u32*)(vlp + c2), *(const u32*)(vlp + c2 + 8) };
            mma16816(o[nt], ahg, bh2);
            mma16816(o[nt], ahg, bl2);
            mma16816(o[nt], alg, bh2);
        }
    }
#pragma unroll
    for (int x = 1; x < 4; x <<= 1) {
        ws0 += __shfl_xor_sync(~0u, ws0, x);
        ws1 += __shfl_xor_sync(~0u, ws1, x);
    }
    if ((lane & 3) == 0) {
        ent[idx0]          = __log2f(L0) + (m0 - ws0) * 1.4426950408889634f;
        ent[idx0 + 8 * Hc] = __log2f(L1) + (m1 - ws1) * 1.4426950408889634f;
    }
    float* op = g_ao + ((size_t)(b * Sc + i0 + g)) * Dc + h * 64;
#pragma unroll
    for (int nt = 0; nt < 8; nt++) {
        *(float2*)(op + nt * 8 + c2)          = make_float2(o[nt][0], o[nt][1]);
        *(float2*)(op + 8 * Dc + nt * 8 + c2) = make_float2(o[nt][2], o[nt][3]);
    }
}

extern "C" void kernel_launch(void* const* d_in, const int* in_sizes, int n_in,
                              void* d_out, int out_size) {
    (void)in_sizes; (void)n_in; (void)out_size;
    const float* x    = (const float*)d_in[0];
    const float* cosb = (const float*)d_in[1];
    const float* sinb = (const float*)d_in[2];
    const float* wsrc[4] = { (const float*)d_in[3], (const float*)d_in[4],
                             (const float*)d_in[5], (const float*)d_in[6] };

    float* out  = (float*)d_out;
    float* attn = out + (size_t)Mc * Dc;
    float* ent  = attn + (size_t)Mc * Hc * (size_t)Sc;

    bf16 *xh, *xl, *wh, *wl, *qh, *ql, *kh, *kl, *aoh, *aol;
    float *q, *k, *v, *ao;
    cudaGetSymbolAddress((void**)&xh, g_xh);   cudaGetSymbolAddress((void**)&xl, g_xl);
    cudaGetSymbolAddress((void**)&wh, g_wh);   cudaGetSymbolAddress((void**)&wl, g_wl);
    cudaGetSymbolAddress((void**)&qh, g_qh);   cudaGetSymbolAddress((void**)&ql, g_ql);
    cudaGetSymbolAddress((void**)&kh, g_kh);   cudaGetSymbolAddress((void**)&kl, g_kl);
    cudaGetSymbolAddress((void**)&aoh, g_aoh); cudaGetSymbolAddress((void**)&aol, g_aol);
    cudaGetSymbolAddress((void**)&q, g_q);     cudaGetSymbolAddress((void**)&k, g_k);
    cudaGetSymbolAddress((void**)&v, g_v);     cudaGetSymbolAddress((void**)&ao, g_ao);

    int n4x = (int)((size_t)Mc * Dc / 4);
    int n4w = Dc * Dc / 4;
    cvt_split<<<n4x / 256, 256>>>(x, xh, xl, n4x);
    for (int i = 0; i < 4; i++)
        cvt_split<<<n4w / 256, 256>>>(wsrc[i], wh + (size_t)i * Dc * Dc, wl + (size_t)i * Dc * Dc, n4w);

    dim3 gproj(Dc / 128, Mc / 128);
    gemm_bf3<<<gproj, 256>>>(xh, xl, wh + 0 * (size_t)Dc * Dc, wl + 0 * (size_t)Dc * Dc, q);
    gemm_bf3<<<gproj, 256>>>(xh, xl, wh + 1 * (size_t)Dc * Dc, wl + 1 * (size_t)Dc * Dc, k);
    gemm_bf3<<<gproj, 256>>>(xh, xl, wh + 2 * (size_t)Dc * Dc, wl + 2 * (size_t)Dc * Dc, v);
    rope_kernel<<<dim3((Bc * Sc * Hc * 32) / 256, 2), 256>>>(cosb, sinb);
    cvt_split<<<n4x / 256, 256>>>(q, qh, ql, n4x);
    cvt_split<<<n4x / 256, 256>>>(k, kh, kl, n4x);
    vtrans<<<dim3(Sc / 32, Dc / 32, Bc), 256>>>();
    attn1<<<dim3(Sc / 128, Bc * Hc), 256>>>(attn);
    attn2<<<dim3(Sc / 128, Bc * Hc), 256>>>(attn, ent);
    cvt_split<<<n4x / 256, 256>>>(ao, aoh, aol, n4x);
    gemm_bf3<<<gproj, 256>>>(aoh, aol, wh + 3 * (size_t)Dc * Dc, wl + 3 * (size_t)Dc * Dc, out);
}

// round 6
// speedup vs baseline: 2.3716x; 2.2614x over previous
#include <cuda_runtime.h>
#include <cuda_bf16.h>
#include <cuda_fp16.h>

#define Bc 2
#define Sc 2048
#define Dc 1024
#define Hc 16
#define Mc (Bc*Sc)

typedef unsigned u32;
typedef __nv_bfloat16 bf16;

// ---------------- scratch ----------------
__device__ bf16 g_xh[(size_t)Mc*Dc], g_xl[(size_t)Mc*Dc];
__device__ bf16 g_wh[4*Dc*Dc], g_wl[4*Dc*Dc];
__device__ bf16 g_qh[(size_t)Mc*Dc], g_ql[(size_t)Mc*Dc];
__device__ bf16 g_kh[(size_t)Mc*Dc], g_kl[(size_t)Mc*Dc];
__device__ bf16 g_vth[(size_t)Bc*Dc*Sc], g_vtl[(size_t)Bc*Dc*Sc];
__device__ bf16 g_aoh[(size_t)Mc*Dc], g_aol[(size_t)Mc*Dc];
__device__ float g_q[(size_t)Mc*Dc], g_k[(size_t)Mc*Dc], g_v[(size_t)Mc*Dc], g_ao[(size_t)Mc*Dc];
__device__ float g_m[Mc*Hc], g_l[Mc*Hc];
__device__ __half g_wraw[(size_t)Mc*Hc*Sc];       // w' fp16, frag-native
__device__ float g_mu[(size_t)4096*2048];          // per (warp-group, tile, lane, row-pair) m_used

// ---------------- helpers ----------------
__device__ __forceinline__ void mma16816(float* c, const u32* a, const u32* b) {
    asm volatile("mma.sync.aligned.m16n8k16.row.col.f32.bf16.bf16.f32 "
        "{%0,%1,%2,%3},{%4,%5,%6,%7},{%8,%9},{%0,%1,%2,%3};"
        : "+f"(c[0]), "+f"(c[1]), "+f"(c[2]), "+f"(c[3])
        : "r"(a[0]), "r"(a[1]), "r"(a[2]), "r"(a[3]), "r"(b[0]), "r"(b[1]));
}
__device__ __forceinline__ u32 pkbf(float x, float y) {
    bf16 a = __float2bfloat16(x), b = __float2bfloat16(y);
    return (u32)__bfloat16_as_ushort(a) | ((u32)__bfloat16_as_ushort(b) << 16);
}
__device__ __forceinline__ float bflo(float x) {
    return x - __bfloat162float(__float2bfloat16(x));
}
__device__ __forceinline__ void cpa16(void* s, const void* g) {
    u32 ss = (u32)__cvta_generic_to_shared(s);
    asm volatile("cp.async.ca.shared.global [%0], [%1], 16;" :: "r"(ss), "l"(g));
}
__device__ __forceinline__ void cpcommit() { asm volatile("cp.async.commit_group;"); }
template<int N> __device__ __forceinline__ void cpwait() { asm volatile("cp.async.wait_group %0;" :: "n"(N)); }

// FMA-pipe exp (x <= 0, x >= -87), rel err ~4e-5
__device__ __forceinline__ float fexp(float x) {
    float y = fmaf(x, 1.4426950408889634f, 12582912.0f);
    float n = y - 12582912.0f;
    float f = fmaf(x, 1.4426950408889634f, -n);
    float p = 0.00961812910f;
    p = fmaf(p, f, 0.05550410866f);
    p = fmaf(p, f, 0.24022650696f);
    p = fmaf(p, f, 0.69314718056f);
    p = fmaf(p, f, 1.0f);
    return __int_as_float(__float_as_int(p) + (__float_as_int(y) << 23));
}

// ---------------- conversions ----------------
__global__ __launch_bounds__(256) void cvt_split(const float* __restrict__ in,
                                                 bf16* __restrict__ oh, bf16* __restrict__ ol, int n4) {
    int i = blockIdx.x * 256 + threadIdx.x;
    if (i >= n4) return;
    float4 v = ((const float4*)in)[i];
    ((uint2*)oh)[i] = make_uint2(pkbf(v.x, v.y), pkbf(v.z, v.w));
    ((uint2*)ol)[i] = make_uint2(pkbf(bflo(v.x), bflo(v.y)), pkbf(bflo(v.z), bflo(v.w)));
}

__global__ __launch_bounds__(256) void vtrans() {
    __shared__ float ts[32][33];
    int tx = threadIdx.x & 31, ty = threadIdx.x >> 5;
    int s0 = blockIdx.x * 32, d0 = blockIdx.y * 32, b = blockIdx.z;
#pragma unroll
    for (int i = 0; i < 4; i++)
        ts[ty + i * 8][tx] = g_v[((size_t)(b * Sc + s0 + ty + i * 8)) * Dc + d0 + tx];
    __syncthreads();
#pragma unroll
    for (int i = 0; i < 4; i++) {
        int d = ty + i * 8;
        float v = ts[tx][d];
        size_t o = ((size_t)(b * Dc + d0 + d)) * Sc + s0 + tx;
        g_vth[o] = __float2bfloat16(v);
        g_vtl[o] = __float2bfloat16(bflo(v));
    }
}

__global__ __launch_bounds__(256) void rope_kernel(const float* __restrict__ cosb,
                                                   const float* __restrict__ sinb) {
    int tid = blockIdx.x * 256 + threadIdx.x;
    int i = tid & 31;
    int h = (tid >> 5) & 15;
    int s = (tid >> 9) & 2047;
    int b = tid >> 20;
    float* p = blockIdx.y ? g_k : g_q;
    size_t off = ((size_t)(b * Sc + s)) * Dc + h * 64 + 2 * i;
    float2 t2 = *reinterpret_cast<float2*>(p + off);
    float c = cosb[s * 32 + i], sn = sinb[s * 32 + i];
    *reinterpret_cast<float2*>(p + off) = make_float2(t2.x * c - t2.y * sn, t2.x * sn + t2.y * c);
}

// ---------------- 3-term bf16 GEMM, cp.async 2-stage ----------------
__global__ __launch_bounds__(256) void gemm_bf3(
    const bf16* __restrict__ Ah, const bf16* __restrict__ Al,
    const bf16* __restrict__ Bh, const bf16* __restrict__ Bl,
    float* __restrict__ C) {
    __shared__ bf16 Ahs[2][128][24], Als[2][128][24], Bhs[2][128][24], Bls[2][128][24];
    int t = threadIdx.x, lane = t & 31, w = t >> 5;
    int wm = w & 1, wn = w >> 1;
    int g = lane >> 2, c2 = (lane & 3) * 2;
    int brow = blockIdx.y * 128, bcol = blockIdx.x * 128;
    float acc[4][4][4];
#pragma unroll
    for (int a = 0; a < 4; a++)
#pragma unroll
        for (int b2 = 0; b2 < 4; b2++)
#pragma unroll
            for (int q = 0; q < 4; q++) acc[a][b2][q] = 0.f;

    int lr = t >> 1, lc = (t & 1) * 8;
    const bf16* pah = Ah + (size_t)(brow + lr) * Dc + lc;
    const bf16* pal = Al + (size_t)(brow + lr) * Dc + lc;
    const bf16* pbh = Bh + (size_t)(bcol + lr) * Dc + lc;
    const bf16* pbl = Bl + (size_t)(bcol + lr) * Dc + lc;

#define GLOAD(st, k0) { \
        cpa16(&Ahs[st][lr][lc], pah + (k0)); cpa16(&Als[st][lr][lc], pal + (k0)); \
        cpa16(&Bhs[st][lr][lc], pbh + (k0)); cpa16(&Bls[st][lr][lc], pbl + (k0)); }

    GLOAD(0, 0); cpcommit();
    for (int kt = 0; kt < 64; kt++) {
        if (kt < 63) { GLOAD((kt + 1) & 1, (kt + 1) * 16); cpcommit(); cpwait<1>(); }
        else cpwait<0>();
        __syncthreads();
        int st = kt & 1;
        u32 a_h[4][4], a_l[4][4];
#pragma unroll
        for (int mf = 0; mf < 4; mf++) {
            int ra = wm * 64 + mf * 16 + g;
            a_h[mf][0] = *(const u32*)&Ahs[st][ra][c2];
            a_h[mf][1] = *(const u32*)&Ahs[st][ra + 8][c2];
            a_h[mf][2] = *(const u32*)&Ahs[st][ra][c2 + 8];
            a_h[mf][3] = *(const u32*)&Ahs[st][ra + 8][c2 + 8];
            a_l[mf][0] = *(const u32*)&Als[st][ra][c2];
            a_l[mf][1] = *(const u32*)&Als[st][ra + 8][c2];
            a_l[mf][2] = *(const u32*)&Als[st][ra][c2 + 8];
            a_l[mf][3] = *(const u32*)&Als[st][ra + 8][c2 + 8];
        }
#pragma unroll
        for (int nf = 0; nf < 4; nf++) {
            int rb = wn * 32 + nf * 8 + g;
            u32 b_h[2] = { *(const u32*)&Bhs[st][rb][c2], *(const u32*)&Bhs[st][rb][c2 + 8] };
            u32 b_l[2] = { *(const u32*)&Bls[st][rb][c2], *(const u32*)&Bls[st][rb][c2 + 8] };
#pragma unroll
            for (int mf = 0; mf < 4; mf++) {
                mma16816(acc[mf][nf], a_h[mf], b_h);
                mma16816(acc[mf][nf], a_h[mf], b_l);
                mma16816(acc[mf][nf], a_l[mf], b_h);
            }
        }
        __syncthreads();
    }
#undef GLOAD
#pragma unroll
    for (int mf = 0; mf < 4; mf++)
#pragma unroll
        for (int nf = 0; nf < 4; nf++) {
            int r = brow + wm * 64 + mf * 16 + g;
            int c = bcol + wn * 32 + nf * 8 + c2;
            *(float2*)&C[(size_t)r * Dc + c]       = make_float2(acc[mf][nf][0], acc[mf][nf][1]);
            *(float2*)&C[(size_t)(r + 8) * Dc + c] = make_float2(acc[mf][nf][2], acc[mf][nf][3]);
        }
}

// ---------------- pass 1: scores + softmax stats + w' + entropy ----------------
__global__ __launch_bounds__(256) void attn1(float* __restrict__ ent) {
    __shared__ bf16 Khs[2][64][72], Kls[2][64][72];
    int t = threadIdx.x, lane = t & 31, w = t >> 5;
    int g = lane >> 2, c2 = (lane & 3) * 2;
    int b = blockIdx.y >> 4, h = blockIdx.y & 15;
    int i0 = blockIdx.x * 128 + w * 16;

    const bf16* qh = g_qh + ((size_t)(b * Sc + i0 + g)) * Dc + h * 64;
    const bf16* ql = g_ql + ((size_t)(b * Sc + i0 + g)) * Dc + h * 64;
    u32 ah[4][4], al[4][4];
#pragma unroll
    for (int kf = 0; kf < 4; kf++) {
        ah[kf][0] = *(const u32*)(qh + kf * 16 + c2);
        ah[kf][1] = *(const u32*)(qh + 8 * Dc + kf * 16 + c2);
        ah[kf][2] = *(const u32*)(qh + kf * 16 + c2 + 8);
        ah[kf][3] = *(const u32*)(qh + 8 * Dc + kf * 16 + c2 + 8);
        al[kf][0] = *(const u32*)(ql + kf * 16 + c2);
        al[kf][1] = *(const u32*)(ql + 8 * Dc + kf * 16 + c2);
        al[kf][2] = *(const u32*)(ql + kf * 16 + c2 + 8);
        al[kf][3] = *(const u32*)(ql + 8 * Dc + kf * 16 + c2 + 8);
    }

    int kr = t >> 2, kc = (t & 3) * 16;
    const bf16* kgh = g_kh + ((size_t)(b * Sc + kr)) * Dc + h * 64 + kc;
    const bf16* kgl = g_kl + ((size_t)(b * Sc + kr)) * Dc + h * 64 + kc;

#define KLOAD(st, j0) { \
        cpa16(&Khs[st][kr][kc],     kgh + (size_t)(j0) * Dc); \
        cpa16(&Khs[st][kr][kc + 8], kgh + (size_t)(j0) * Dc + 8); \
        cpa16(&Kls[st][kr][kc],     kgl + (size_t)(j0) * Dc); \
        cpa16(&Kls[st][kr][kc + 8], kgl + (size_t)(j0) * Dc + 8); }

    float m0 = -1e30f, m1 = -1e30f, l0 = 0.f, l1 = 0.f, ws0 = 0.f, ws1 = 0.f;
    size_t wg = ((size_t)blockIdx.y * 16 + blockIdx.x) * 8 + w;
    uint2* wout = (uint2*)g_wraw + wg * 8192;
    float* muout = g_mu + wg * 2048;

    KLOAD(0, 0); cpcommit();
    for (int jt = 0; jt < 32; jt++) {
        int j0 = jt * 64;
        if (jt < 31) { KLOAD((jt + 1) & 1, j0 + 64); cpcommit(); cpwait<1>(); }
        else cpwait<0>();
        __syncthreads();
        int st = jt & 1;
        float sc[8][4];
#pragma unroll
        for (int nt = 0; nt < 8; nt++) {
            float* c = sc[nt];
            c[0] = c[1] = c[2] = c[3] = 0.f;
#pragma unroll
            for (int kf = 0; kf < 4; kf++) {
                u32 bh2[2] = { *(const u32*)&Khs[st][nt * 8 + g][kf * 16 + c2],
                               *(const u32*)&Khs[st][nt * 8 + g][kf * 16 + c2 + 8] };
                u32 bl2[2] = { *(const u32*)&Kls[st][nt * 8 + g][kf * 16 + c2],
                               *(const u32*)&Kls[st][nt * 8 + g][kf * 16 + c2 + 8] };
                mma16816(c, ah[kf], bh2);
                mma16816(c, ah[kf], bl2);
                mma16816(c, al[kf], bh2);
            }
            c[0] *= 0.125f; c[1] *= 0.125f; c[2] *= 0.125f; c[3] *= 0.125f;
        }
        __syncthreads();
        float tm0 = -1e30f, tm1 = -1e30f;
#pragma unroll
        for (int nt = 0; nt < 8; nt++) {
            tm0 = fmaxf(tm0, fmaxf(sc[nt][0], sc[nt][1]));
            tm1 = fmaxf(tm1, fmaxf(sc[nt][2], sc[nt][3]));
        }
        float mn0 = fmaxf(m0, tm0), mn1 = fmaxf(m1, tm1);
        float cr0 = __expf(m0 - mn0), cr1 = __expf(m1 - mn1);
        l0 *= cr0; ws0 *= cr0; l1 *= cr1; ws1 *= cr1;
#pragma unroll
        for (int nt = 0; nt < 8; nt++) {
            float e0 = fexp(sc[nt][0] - mn0), e1 = fexp(sc[nt][1] - mn0);     // FMA pipe
            float e2 = __expf(sc[nt][2] - mn1), e3 = __expf(sc[nt][3] - mn1); // MUFU pipe
            l0 += e0 + e1;
            ws0 = fmaf(e0, sc[nt][0], fmaf(e1, sc[nt][1], ws0));
            l1 += e2 + e3;
            ws1 = fmaf(e2, sc[nt][2], fmaf(e3, sc[nt][3], ws1));
            __half2 p01 = __floats2half2_rn(e0, e1);
            __half2 p23 = __floats2half2_rn(e2, e3);
            wout[(size_t)(j0 / 8 + nt) * 32 + lane] =
                make_uint2(*(u32*)&p01, *(u32*)&p23);
        }
        m0 = mn0; m1 = mn1;
        muout[jt * 64 + lane * 2]     = mn0;
        muout[jt * 64 + lane * 2 + 1] = mn1;
    }
#undef KLOAD
#pragma unroll
    for (int o = 1; o < 4; o <<= 1) {
        float om = __shfl_xor_sync(~0u, m0, o), ol = __shfl_xor_sync(~0u, l0, o),
              ow = __shfl_xor_sync(~0u, ws0, o);
        float mn = fmaxf(m0, om), ca = __expf(m0 - mn), cb = __expf(om - mn);
        l0 = l0 * ca + ol * cb; ws0 = ws0 * ca + ow * cb; m0 = mn;
        om = __shfl_xor_sync(~0u, m1, o); ol = __shfl_xor_sync(~0u, l1, o);
        ow = __shfl_xor_sync(~0u, ws1, o);
        mn = fmaxf(m1, om); ca = __expf(m1 - mn); cb = __expf(om - mn);
        l1 = l1 * ca + ol * cb; ws1 = ws1 * ca + ow * cb; m1 = mn;
    }
    if ((lane & 3) == 0) {
        int idx0 = (b * Sc + i0 + g) * Hc + h;
        g_m[idx0] = m0; g_l[idx0] = l0;
        g_m[idx0 + 8 * Hc] = m1; g_l[idx0 + 8 * Hc] = l1;
        ent[idx0]          = __log2f(l0) + (m0 - ws0 / l0) * 1.4426950408889634f;
        ent[idx0 + 8 * Hc] = __log2f(l1) + (m1 - ws1 / l1) * 1.4426950408889634f;
    }
}

// ---------------- pass 2: w = w'*corr, write canonical, AV mma ----------------
__global__ __launch_bounds__(128) void attn2(float* __restrict__ attnw) {
    __shared__ bf16 Vhs[64][72], Vls[64][72];
    __shared__ float Ws[64][68];
    int t = threadIdx.x, lane = t & 31, w = t >> 5;
    int g = lane >> 2, c2 = (lane & 3) * 2;
    int b = blockIdx.y >> 4, h = blockIdx.y & 15;
    int ib = blockIdx.x;
    int i0 = ib * 64;
    int iw = i0 + w * 16;
    size_t wg = ((size_t)blockIdx.y * 16 + (ib >> 1)) * 8 + (ib & 1) * 4 + w;
    const uint2* win = (const uint2*)g_wraw + wg * 8192;
    const float* muin = g_mu + wg * 2048;
    int idx0 = (b * Sc + iw + g) * Hc + h;
    float m0 = g_m[idx0], li0 = 1.f / g_l[idx0];
    float m1 = g_m[idx0 + 8 * Hc], li1 = 1.f / g_l[idx0 + 8 * Hc];

    int vr = t >> 1, vc = (t & 1) * 32;
    const bf16* vgh = g_vth + ((size_t)(b * Dc + h * 64 + vr)) * Sc + vc;
    const bf16* vgl = g_vtl + ((size_t)(b * Dc + h * 64 + vr)) * Sc + vc;

    float o[8][4];
#pragma unroll
    for (int n = 0; n < 8; n++)
#pragma unroll
        for (int q = 0; q < 4; q++) o[n][q] = 0.f;

    for (int jt = 0; jt < 32; jt++) {
        int j0 = jt * 64;
        __syncthreads();
#pragma unroll
        for (int c = 0; c < 32; c += 8) {
            cpa16(&Vhs[vr][vc + c], vgh + j0 + c);
            cpa16(&Vls[vr][vc + c], vgl + j0 + c);
        }
        cpcommit();

        float cc0 = __expf(muin[jt * 64 + lane * 2]     - m0) * li0;
        float cc1 = __expf(muin[jt * 64 + lane * 2 + 1] - m1) * li1;

        float wv[8][4];
#pragma unroll
        for (int ff = 0; ff < 8; ff++) {
            uint2 pw = win[(size_t)(j0 / 8 + ff) * 32 + lane];
            float2 p01 = __half22float2(*(__half2*)&pw.x);
            float2 p23 = __half22float2(*(__half2*)&pw.y);
            wv[ff][0] = p01.x * cc0; wv[ff][1] = p01.y * cc0;
            wv[ff][2] = p23.x * cc1; wv[ff][3] = p23.y * cc1;
            int ro = w * 16 + g;
            Ws[ro][ff * 8 + c2]         = wv[ff][0];
            Ws[ro][ff * 8 + c2 + 1]     = wv[ff][1];
            Ws[ro + 8][ff * 8 + c2]     = wv[ff][2];
            Ws[ro + 8][ff * 8 + c2 + 1] = wv[ff][3];
        }
        u32 ahg[4][4], alg[4][4];
#pragma unroll
        for (int kf = 0; kf < 4; kf++) {
            ahg[kf][0] = pkbf(wv[2*kf][0], wv[2*kf][1]);
            ahg[kf][1] = pkbf(wv[2*kf][2], wv[2*kf][3]);
            ahg[kf][2] = pkbf(wv[2*kf+1][0], wv[2*kf+1][1]);
            ahg[kf][3] = pkbf(wv[2*kf+1][2], wv[2*kf+1][3]);
            alg[kf][0] = pkbf(bflo(wv[2*kf][0]), bflo(wv[2*kf][1]));
            alg[kf][1] = pkbf(bflo(wv[2*kf][2]), bflo(wv[2*kf][3]));
            alg[kf][2] = pkbf(bflo(wv[2*kf+1][0]), bflo(wv[2*kf+1][1]));
            alg[kf][3] = pkbf(bflo(wv[2*kf+1][2]), bflo(wv[2*kf+1][3]));
        }
        cpwait<0>();
        __syncthreads();
#pragma unroll
        for (int r8 = 0; r8 < 8; r8++) {
            int id = t + r8 * 128;
            int row = id >> 4, c4 = (id & 15) * 4;
            *(float4*)(attnw + ((size_t)((b * Sc + i0 + row) * Hc + h)) * Sc + j0 + c4) =
                *(float4*)&Ws[row][c4];
        }
#pragma unroll
        for (int nt = 0; nt < 8; nt++) {
#pragma unroll
            for (int kf = 0; kf < 4; kf++) {
                u32 bh2[2] = { *(const u32*)&Vhs[nt * 8 + g][kf * 16 + c2],
                               *(const u32*)&Vhs[nt * 8 + g][kf * 16 + c2 + 8] };
                u32 bl2[2] = { *(const u32*)&Vls[nt * 8 + g][kf * 16 + c2],
                               *(const u32*)&Vls[nt * 8 + g][kf * 16 + c2 + 8] };
                mma16816(o[nt], ahg[kf], bh2);
                mma16816(o[nt], ahg[kf], bl2);
                mma16816(o[nt], alg[kf], bh2);
            }
        }
    }
    float* op = g_ao + ((size_t)(b * Sc + iw + g)) * Dc + h * 64;
#pragma unroll
    for (int nt = 0; nt < 8; nt++) {
        *(float2*)(op + nt * 8 + c2)          = make_float2(o[nt][0], o[nt][1]);
        *(float2*)(op + 8 * Dc + nt * 8 + c2) = make_float2(o[nt][2], o[nt][3]);
    }
}

extern "C" void kernel_launch(void* const* d_in, const int* in_sizes, int n_in,
                              void* d_out, int out_size) {
    (void)in_sizes; (void)n_in; (void)out_size;
    const float* x    = (const float*)d_in[0];
    const float* cosb = (const float*)d_in[1];
    const float* sinb = (const float*)d_in[2];
    const float* wsrc[4] = { (const float*)d_in[3], (const float*)d_in[4],
                             (const float*)d_in[5], (const float*)d_in[6] };

    float* out  = (float*)d_out;
    float* attn = out + (size_t)Mc * Dc;
    float* ent  = attn + (size_t)Mc * Hc * (size_t)Sc;

    bf16 *xh, *xl, *wh, *wl, *qh, *ql, *kh, *kl, *aoh, *aol;
    float *q, *k, *v, *ao;
    cudaGetSymbolAddress((void**)&xh, g_xh);   cudaGetSymbolAddress((void**)&xl, g_xl);
    cudaGetSymbolAddress((void**)&wh, g_wh);   cudaGetSymbolAddress((void**)&wl, g_wl);
    cudaGetSymbolAddress((void**)&qh, g_qh);   cudaGetSymbolAddress((void**)&ql, g_ql);
    cudaGetSymbolAddress((void**)&kh, g_kh);   cudaGetSymbolAddress((void**)&kl, g_kl);
    cudaGetSymbolAddress((void**)&aoh, g_aoh); cudaGetSymbolAddress((void**)&aol, g_aol);
    cudaGetSymbolAddress((void**)&q, g_q);     cudaGetSymbolAddress((void**)&k, g_k);
    cudaGetSymbolAddress((void**)&v, g_v);     cudaGetSymbolAddress((void**)&ao, g_ao);

    int n4x = (int)((size_t)Mc * Dc / 4);
    int n4w = Dc * Dc / 4;
    cvt_split<<<n4x / 256, 256>>>(x, xh, xl, n4x);
    for (int i = 0; i < 4; i++)
        cvt_split<<<n4w / 256, 256>>>(wsrc[i], wh + (size_t)i * Dc * Dc, wl + (size_t)i * Dc * Dc, n4w);

    dim3 gproj(Dc / 128, Mc / 128);
    gemm_bf3<<<gproj, 256>>>(xh, xl, wh + 0 * (size_t)Dc * Dc, wl + 0 * (size_t)Dc * Dc, q);
    gemm_bf3<<<gproj, 256>>>(xh, xl, wh + 1 * (size_t)Dc * Dc, wl + 1 * (size_t)Dc * Dc, k);
    gemm_bf3<<<gproj, 256>>>(xh, xl, wh + 2 * (size_t)Dc * Dc, wl + 2 * (size_t)Dc * Dc, v);
    rope_kernel<<<dim3((Bc * Sc * Hc * 32) / 256, 2), 256>>>(cosb, sinb);
    cvt_split<<<n4x / 256, 256>>>(q, qh, ql, n4x);
    cvt_split<<<n4x / 256, 256>>>(k, kh, kl, n4x);
    vtrans<<<dim3(Sc / 32, Dc / 32, Bc), 256>>>();
    attn1<<<dim3(Sc / 128, Bc * Hc), 256>>>(ent);
    attn2<<<dim3(Sc / 64, Bc * Hc), 128>>>(attn);
    cvt_split<<<n4x / 256, 256>>>(ao, aoh, aol, n4x);
    gemm_bf3<<<gproj, 256>>>(aoh, aol, wh + 3 * (size_t)Dc * Dc, wl + 3 * (size_t)Dc * Dc, out);
}

// round 8
// speedup vs baseline: 2.4589x; 1.0368x over previous
#include <cuda_runtime.h>
#include <cuda_bf16.h>
#include <cuda_fp16.h>

#define Bc 2
#define Sc 2048
#define Dc 1024
#define Hc 16
#define Mc (Bc*Sc)

typedef unsigned u32;
typedef __nv_bfloat16 bf16;

// ---------------- scratch ----------------
__device__ bf16 g_xh[(size_t)Mc*Dc], g_xl[(size_t)Mc*Dc];
__device__ bf16 g_wh[4*Dc*Dc], g_wl[4*Dc*Dc];
__device__ bf16 g_qh[(size_t)Mc*Dc], g_ql[(size_t)Mc*Dc];
__device__ bf16 g_kh[(size_t)Mc*Dc], g_kl[(size_t)Mc*Dc];
__device__ __half g_vth[(size_t)Bc*Dc*Sc], g_vtl[(size_t)Bc*Dc*Sc];
__device__ bf16 g_aoh[(size_t)Mc*Dc], g_aol[(size_t)Mc*Dc];
__device__ float g_v[(size_t)Mc*Dc];
__device__ float g_m[Mc*Hc], g_l[Mc*Hc];
__device__ __half g_wraw[(size_t)Mc*Hc*Sc];   // w' fp16, frag-native
__device__ float g_mu[(size_t)4096*512];       // per (wg, tile, row) m_used

// ---------------- helpers ----------------
__device__ __forceinline__ void mma16816(float* c, const u32* a, const u32* b) {
    asm volatile("mma.sync.aligned.m16n8k16.row.col.f32.bf16.bf16.f32 "
        "{%0,%1,%2,%3},{%4,%5,%6,%7},{%8,%9},{%0,%1,%2,%3};"
        : "+f"(c[0]), "+f"(c[1]), "+f"(c[2]), "+f"(c[3])
        : "r"(a[0]), "r"(a[1]), "r"(a[2]), "r"(a[3]), "r"(b[0]), "r"(b[1]));
}
__device__ __forceinline__ void mma16816h(float* c, const u32* a, const u32* b) {
    asm volatile("mma.sync.aligned.m16n8k16.row.col.f32.f16.f16.f32 "
        "{%0,%1,%2,%3},{%4,%5,%6,%7},{%8,%9},{%0,%1,%2,%3};"
        : "+f"(c[0]), "+f"(c[1]), "+f"(c[2]), "+f"(c[3])
        : "r"(a[0]), "r"(a[1]), "r"(a[2]), "r"(a[3]), "r"(b[0]), "r"(b[1]));
}
__device__ __forceinline__ u32 pkbf(float x, float y) {
    bf16 a = __float2bfloat16(x), b = __float2bfloat16(y);
    return (u32)__bfloat16_as_ushort(a) | ((u32)__bfloat16_as_ushort(b) << 16);
}
__device__ __forceinline__ u32 pkh(float x, float y) {
    __half2 h = __floats2half2_rn(x, y);
    return *(u32*)&h;
}
__device__ __forceinline__ float bflo(float x) {
    return x - __bfloat162float(__float2bfloat16(x));
}
__device__ __forceinline__ void cpa16(void* s, const void* g) {
    u32 ss = (u32)__cvta_generic_to_shared(s);
    asm volatile("cp.async.ca.shared.global [%0], [%1], 16;" :: "r"(ss), "l"(g));
}
__device__ __forceinline__ void cpcommit() { asm volatile("cp.async.commit_group;"); }
template<int N> __device__ __forceinline__ void cpwait() { asm volatile("cp.async.wait_group %0;" :: "n"(N)); }

// FMA-pipe exp (x <= 0), rel err ~4e-5
__device__ __forceinline__ float fexp(float x) {
    float y = fmaf(x, 1.4426950408889634f, 12582912.0f);
    float n = y - 12582912.0f;
    float f = fmaf(x, 1.4426950408889634f, -n);
    float p = 0.00961812910f;
    p = fmaf(p, f, 0.05550410866f);
    p = fmaf(p, f, 0.24022650696f);
    p = fmaf(p, f, 0.69314718056f);
    p = fmaf(p, f, 1.0f);
    return __int_as_float(__float_as_int(p) + (__float_as_int(y) << 23));
}

// ---------------- conversions ----------------
__global__ __launch_bounds__(256) void cvt_split(const float* __restrict__ in,
                                                 bf16* __restrict__ oh, bf16* __restrict__ ol, int n4) {
    int i = blockIdx.x * 256 + threadIdx.x;
    if (i >= n4) return;
    float4 v = ((const float4*)in)[i];
    ((uint2*)oh)[i] = make_uint2(pkbf(v.x, v.y), pkbf(v.z, v.w));
    ((uint2*)ol)[i] = make_uint2(pkbf(bflo(v.x), bflo(v.y)), pkbf(bflo(v.z), bflo(v.w)));
}

__global__ __launch_bounds__(256) void vtrans() {
    __shared__ float ts[32][33];
    int tx = threadIdx.x & 31, ty = threadIdx.x >> 5;
    int s0 = blockIdx.x * 32, d0 = blockIdx.y * 32, b = blockIdx.z;
#pragma unroll
    for (int i = 0; i < 4; i++)
        ts[ty + i * 8][tx] = g_v[((size_t)(b * Sc + s0 + ty + i * 8)) * Dc + d0 + tx];
    __syncthreads();
#pragma unroll
    for (int i = 0; i < 4; i++) {
        int d = ty + i * 8;
        float v = ts[tx][d];
        size_t o = ((size_t)(b * Dc + d0 + d)) * Sc + s0 + tx;
        __half vh = __float2half(v);
        g_vth[o] = vh;
        g_vtl[o] = __float2half(v - __half2float(vh));
    }
}

// ---------------- 3-term bf16 GEMM, cp.async 2-stage ----------------
// mode 0: rope + bf16 hi/lo split -> Ch/Cl (Q,K).  mode 1: fp32 -> Cf (V, out)
__global__ __launch_bounds__(256) void gemm_bf3(
    const bf16* __restrict__ Ah, const bf16* __restrict__ Al,
    const bf16* __restrict__ Bh, const bf16* __restrict__ Bl,
    bf16* __restrict__ Ch, bf16* __restrict__ Cl, float* __restrict__ Cf,
    const float* __restrict__ cosb, const float* __restrict__ sinb, int mode) {
    __shared__ bf16 Ahs[2][128][24], Als[2][128][24], Bhs[2][128][24], Bls[2][128][24];
    int t = threadIdx.x, lane = t & 31, w = t >> 5;
    int wm = w & 1, wn = w >> 1;
    int g = lane >> 2, c2 = (lane & 3) * 2;
    int brow = blockIdx.y * 128, bcol = blockIdx.x * 128;
    float acc[4][4][4];
#pragma unroll
    for (int a = 0; a < 4; a++)
#pragma unroll
        for (int b2 = 0; b2 < 4; b2++)
#pragma unroll
            for (int q = 0; q < 4; q++) acc[a][b2][q] = 0.f;

    int lr = t >> 1, lc = (t & 1) * 8;
    const bf16* pah = Ah + (size_t)(brow + lr) * Dc + lc;
    const bf16* pal = Al + (size_t)(brow + lr) * Dc + lc;
    const bf16* pbh = Bh + (size_t)(bcol + lr) * Dc + lc;
    const bf16* pbl = Bl + (size_t)(bcol + lr) * Dc + lc;

#define GLOAD(st, k0) { \
        cpa16(&Ahs[st][lr][lc], pah + (k0)); cpa16(&Als[st][lr][lc], pal + (k0)); \
        cpa16(&Bhs[st][lr][lc], pbh + (k0)); cpa16(&Bls[st][lr][lc], pbl + (k0)); }

    GLOAD(0, 0); cpcommit();
    for (int kt = 0; kt < 64; kt++) {
        if (kt < 63) { GLOAD((kt + 1) & 1, (kt + 1) * 16); cpcommit(); cpwait<1>(); }
        else cpwait<0>();
        __syncthreads();
        int st = kt & 1;
        u32 a_h[4][4], a_l[4][4];
#pragma unroll
        for (int mf = 0; mf < 4; mf++) {
            int ra = wm * 64 + mf * 16 + g;
            a_h[mf][0] = *(const u32*)&Ahs[st][ra][c2];
            a_h[mf][1] = *(const u32*)&Ahs[st][ra + 8][c2];
            a_h[mf][2] = *(const u32*)&Ahs[st][ra][c2 + 8];
            a_h[mf][3] = *(const u32*)&Ahs[st][ra + 8][c2 + 8];
            a_l[mf][0] = *(const u32*)&Als[st][ra][c2];
            a_l[mf][1] = *(const u32*)&Als[st][ra + 8][c2];
            a_l[mf][2] = *(const u32*)&Als[st][ra][c2 + 8];
            a_l[mf][3] = *(const u32*)&Als[st][ra + 8][c2 + 8];
        }
#pragma unroll
        for (int nf = 0; nf < 4; nf++) {
            int rb = wn * 32 + nf * 8 + g;
            u32 b_h[2] = { *(const u32*)&Bhs[st][rb][c2], *(const u32*)&Bhs[st][rb][c2 + 8] };
            u32 b_l[2] = { *(const u32*)&Bls[st][rb][c2], *(const u32*)&Bls[st][rb][c2 + 8] };
#pragma unroll
            for (int mf = 0; mf < 4; mf++) {
                mma16816(acc[mf][nf], a_h[mf], b_h);
                mma16816(acc[mf][nf], a_h[mf], b_l);
                mma16816(acc[mf][nf], a_l[mf], b_h);
            }
        }
        __syncthreads();
    }
#undef GLOAD
    if (mode == 1) {
#pragma unroll
        for (int mf = 0; mf < 4; mf++)
#pragma unroll
            for (int nf = 0; nf < 4; nf++) {
                int r = brow + wm * 64 + mf * 16 + g;
                int c = bcol + wn * 32 + nf * 8 + c2;
                *(float2*)&Cf[(size_t)r * Dc + c]       = make_float2(acc[mf][nf][0], acc[mf][nf][1]);
                *(float2*)&Cf[(size_t)(r + 8) * Dc + c] = make_float2(acc[mf][nf][2], acc[mf][nf][3]);
            }
    } else {
#pragma unroll
        for (int mf = 0; mf < 4; mf++)
#pragma unroll
            for (int nf = 0; nf < 4; nf++) {
                int r = brow + wm * 64 + mf * 16 + g;
                int c = bcol + wn * 32 + nf * 8 + c2;
                int pi = (c & 63) >> 1;
                int sA = r & 2047, sB = (r + 8) & 2047;
                float csA = cosb[sA * 32 + pi], snA = sinb[sA * 32 + pi];
                float csB = cosb[sB * 32 + pi], snB = sinb[sB * 32 + pi];
                float a0 = acc[mf][nf][0], a1 = acc[mf][nf][1];
                float a2 = acc[mf][nf][2], a3 = acc[mf][nf][3];
                float o0 = a0 * csA - a1 * snA, o1 = a0 * snA + a1 * csA;
                float o2 = a2 * csB - a3 * snB, o3 = a2 * snB + a3 * csB;
                size_t off = (size_t)r * Dc + c;
                *(u32*)(Ch + off) = pkbf(o0, o1);
                *(u32*)(Cl + off) = pkbf(bflo(o0), bflo(o1));
                off = (size_t)(r + 8) * Dc + c;
                *(u32*)(Ch + off) = pkbf(o2, o3);
                *(u32*)(Cl + off) = pkbf(bflo(o2), bflo(o3));
            }
    }
}

// ---------------- pass 1: scores + softmax stats + w' + entropy ----------------
__global__ __launch_bounds__(256) void attn1(float* __restrict__ ent) {
    __shared__ bf16 Khs[2][64][72], Kls[2][64][72];
    int t = threadIdx.x, lane = t & 31, w = t >> 5;
    int g = lane >> 2, c2 = (lane & 3) * 2;
    int b = blockIdx.y >> 4, h = blockIdx.y & 15;
    int i0 = blockIdx.x * 128 + w * 16;

    const bf16* qh = g_qh + ((size_t)(b * Sc + i0 + g)) * Dc + h * 64;
    const bf16* ql = g_ql + ((size_t)(b * Sc + i0 + g)) * Dc + h * 64;
    u32 ah[4][4], al[4][4];
#pragma unroll
    for (int kf = 0; kf < 4; kf++) {
        ah[kf][0] = *(const u32*)(qh + kf * 16 + c2);
        ah[kf][1] = *(const u32*)(qh + 8 * Dc + kf * 16 + c2);
        ah[kf][2] = *(const u32*)(qh + kf * 16 + c2 + 8);
        ah[kf][3] = *(const u32*)(qh + 8 * Dc + kf * 16 + c2 + 8);
        al[kf][0] = *(const u32*)(ql + kf * 16 + c2);
        al[kf][1] = *(const u32*)(ql + 8 * Dc + kf * 16 + c2);
        al[kf][2] = *(const u32*)(ql + kf * 16 + c2 + 8);
        al[kf][3] = *(const u32*)(ql + 8 * Dc + kf * 16 + c2 + 8);
    }

    int kr = t >> 2, kc = (t & 3) * 16;
    const bf16* kgh = g_kh + ((size_t)(b * Sc + kr)) * Dc + h * 64 + kc;
    const bf16* kgl = g_kl + ((size_t)(b * Sc + kr)) * Dc + h * 64 + kc;

#define KLOAD(st, j0) { \
        cpa16(&Khs[st][kr][kc],     kgh + (size_t)(j0) * Dc); \
        cpa16(&Khs[st][kr][kc + 8], kgh + (size_t)(j0) * Dc + 8); \
        cpa16(&Kls[st][kr][kc],     kgl + (size_t)(j0) * Dc); \
        cpa16(&Kls[st][kr][kc + 8], kgl + (size_t)(j0) * Dc + 8); }

    float m0 = -1e30f, m1 = -1e30f, l0 = 0.f, l1 = 0.f, ws0 = 0.f, ws1 = 0.f;
    size_t wg = ((size_t)blockIdx.y * 16 + blockIdx.x) * 8 + w;
    uint2* wout = (uint2*)g_wraw + wg * 8192;
    float* muout = g_mu + wg * 512;

    KLOAD(0, 0); cpcommit();
    for (int jt = 0; jt < 32; jt++) {
        int j0 = jt * 64;
        if (jt < 31) { KLOAD((jt + 1) & 1, j0 + 64); cpcommit(); cpwait<1>(); }
        else cpwait<0>();
        __syncthreads();
        int st = jt & 1;
        float sc[8][4];
#pragma unroll
        for (int nt = 0; nt < 8; nt++) {
            float* c = sc[nt];
            c[0] = c[1] = c[2] = c[3] = 0.f;
#pragma unroll
            for (int kf = 0; kf < 4; kf++) {
                u32 bh2[2] = { *(const u32*)&Khs[st][nt * 8 + g][kf * 16 + c2],
                               *(const u32*)&Khs[st][nt * 8 + g][kf * 16 + c2 + 8] };
                u32 bl2[2] = { *(const u32*)&Kls[st][nt * 8 + g][kf * 16 + c2],
                               *(const u32*)&Kls[st][nt * 8 + g][kf * 16 + c2 + 8] };
                mma16816(c, ah[kf], bh2);
                mma16816(c, ah[kf], bl2);
                mma16816(c, al[kf], bh2);
            }
            c[0] *= 0.125f; c[1] *= 0.125f; c[2] *= 0.125f; c[3] *= 0.125f;
        }
        __syncthreads();
        float tm0 = -1e30f, tm1 = -1e30f;
#pragma unroll
        for (int nt = 0; nt < 8; nt++) {
            tm0 = fmaxf(tm0, fmaxf(sc[nt][0], sc[nt][1]));
            tm1 = fmaxf(tm1, fmaxf(sc[nt][2], sc[nt][3]));
        }
        // make the running max row-uniform across the 4 lanes of each row
        tm0 = fmaxf(tm0, __shfl_xor_sync(~0u, tm0, 1));
        tm0 = fmaxf(tm0, __shfl_xor_sync(~0u, tm0, 2));
        tm1 = fmaxf(tm1, __shfl_xor_sync(~0u, tm1, 1));
        tm1 = fmaxf(tm1, __shfl_xor_sync(~0u, tm1, 2));
        float mn0 = fmaxf(m0, tm0), mn1 = fmaxf(m1, tm1);
        float cr0 = __expf(m0 - mn0), cr1 = __expf(m1 - mn1);
        l0 *= cr0; ws0 *= cr0; l1 *= cr1; ws1 *= cr1;
#pragma unroll
        for (int nt = 0; nt < 8; nt++) {
            float e0 = fexp(sc[nt][0] - mn0), e1 = fexp(sc[nt][1] - mn0);     // FMA pipe
            float e2 = __expf(sc[nt][2] - mn1), e3 = __expf(sc[nt][3] - mn1); // MUFU pipe
            l0 += e0 + e1;
            ws0 = fmaf(e0, sc[nt][0], fmaf(e1, sc[nt][1], ws0));
            l1 += e2 + e3;
            ws1 = fmaf(e2, sc[nt][2], fmaf(e3, sc[nt][3], ws1));
            __half2 p01 = __floats2half2_rn(e0, e1);
            __half2 p23 = __floats2half2_rn(e2, e3);
            wout[(size_t)(j0 / 8 + nt) * 32 + lane] = make_uint2(*(u32*)&p01, *(u32*)&p23);
        }
        m0 = mn0; m1 = mn1;
        if ((lane & 3) == 0) {
            muout[jt * 16 + g * 2]     = mn0;
            muout[jt * 16 + g * 2 + 1] = mn1;
        }
    }
#undef KLOAD
#pragma unroll
    for (int o = 1; o < 4; o <<= 1) {
        float om = __shfl_xor_sync(~0u, m0, o), ol = __shfl_xor_sync(~0u, l0, o),
              ow = __shfl_xor_sync(~0u, ws0, o);
        float mn = fmaxf(m0, om), ca = __expf(m0 - mn), cb = __expf(om - mn);
        l0 = l0 * ca + ol * cb; ws0 = ws0 * ca + ow * cb; m0 = mn;
        om = __shfl_xor_sync(~0u, m1, o); ol = __shfl_xor_sync(~0u, l1, o);
        ow = __shfl_xor_sync(~0u, ws1, o);
        mn = fmaxf(m1, om); ca = __expf(m1 - mn); cb = __expf(om - mn);
        l1 = l1 * ca + ol * cb; ws1 = ws1 * ca + ow * cb; m1 = mn;
    }
    if ((lane & 3) == 0) {
        int idx0 = (b * Sc + i0 + g) * Hc + h;
        g_m[idx0] = m0; g_l[idx0] = l0;
        g_m[idx0 + 8 * Hc] = m1; g_l[idx0 + 8 * Hc] = l1;
        ent[idx0]          = __log2f(l0) + (m0 - ws0 / l0) * 1.4426950408889634f;
        ent[idx0 + 8 * Hc] = __log2f(l1) + (m1 - ws1 / l1) * 1.4426950408889634f;
    }
}

// ---------------- pass 2: w = w'*corr -> out, AV fp16 2-term, bf16 split o ----------------
__global__ __launch_bounds__(128) void attn2(float* __restrict__ attnw) {
    __shared__ __half Vhs[64][72], Vls[64][72];
    __shared__ float Ws[64][68];
    int t = threadIdx.x, lane = t & 31, w = t >> 5;
    int g = lane >> 2, c2 = (lane & 3) * 2;
    int b = blockIdx.y >> 4, h = blockIdx.y & 15;
    int ib = blockIdx.x;
    int i0 = ib * 64;
    int iw = i0 + w * 16;
    size_t wg = ((size_t)blockIdx.y * 16 + (ib >> 1)) * 8 + (ib & 1) * 4 + w;
    const uint2* win = (const uint2*)g_wraw + wg * 8192;
    const float* muin = g_mu + wg * 512;
    int idx0 = (b * Sc + iw + g) * Hc + h;
    float m0 = g_m[idx0], li0 = 1.f / g_l[idx0];
    float m1 = g_m[idx0 + 8 * Hc], li1 = 1.f / g_l[idx0 + 8 * Hc];

    int vr = t >> 1, vc = (t & 1) * 32;
    const __half* vgh = g_vth + ((size_t)(b * Dc + h * 64 + vr)) * Sc + vc;
    const __half* vgl = g_vtl + ((size_t)(b * Dc + h * 64 + vr)) * Sc + vc;

    float o[8][4];
#pragma unroll
    for (int n = 0; n < 8; n++)
#pragma unroll
        for (int q = 0; q < 4; q++) o[n][q] = 0.f;

    for (int jt = 0; jt < 32; jt++) {
        int j0 = jt * 64;
        __syncthreads();
#pragma unroll
        for (int c = 0; c < 32; c += 8) {
            cpa16(&Vhs[vr][vc + c], vgh + j0 + c);
            cpa16(&Vls[vr][vc + c], vgl + j0 + c);
        }
        cpcommit();

        float cc0 = __expf(muin[jt * 16 + g * 2]     - m0) * li0;
        float cc1 = __expf(muin[jt * 16 + g * 2 + 1] - m1) * li1;

        float wv[8][4];
#pragma unroll
        for (int ff = 0; ff < 8; ff++) {
            uint2 pw = win[(size_t)(j0 / 8 + ff) * 32 + lane];
            float2 p01 = __half22float2(*(__half2*)&pw.x);
            float2 p23 = __half22float2(*(__half2*)&pw.y);
            wv[ff][0] = p01.x * cc0; wv[ff][1] = p01.y * cc0;
            wv[ff][2] = p23.x * cc1; wv[ff][3] = p23.y * cc1;
            int ro = w * 16 + g;
            Ws[ro][ff * 8 + c2]         = wv[ff][0];
            Ws[ro][ff * 8 + c2 + 1]     = wv[ff][1];
            Ws[ro + 8][ff * 8 + c2]     = wv[ff][2];
            Ws[ro + 8][ff * 8 + c2 + 1] = wv[ff][3];
        }
        u32 ahg[4][4];
#pragma unroll
        for (int kf = 0; kf < 4; kf++) {
            ahg[kf][0] = pkh(wv[2*kf][0], wv[2*kf][1]);
            ahg[kf][1] = pkh(wv[2*kf][2], wv[2*kf][3]);
            ahg[kf][2] = pkh(wv[2*kf+1][0], wv[2*kf+1][1]);
            ahg[kf][3] = pkh(wv[2*kf+1][2], wv[2*kf+1][3]);
        }
        cpwait<0>();
        __syncthreads();
#pragma unroll
        for (int r8 = 0; r8 < 8; r8++) {
            int id = t + r8 * 128;
            int row = id >> 4, c4 = (id & 15) * 4;
            *(float4*)(attnw + ((size_t)((b * Sc + i0 + row) * Hc + h)) * Sc + j0 + c4) =
                *(float4*)&Ws[row][c4];
        }
#pragma unroll
        for (int nt = 0; nt < 8; nt++) {
#pragma unroll
            for (int kf = 0; kf < 4; kf++) {
                u32 bh2[2] = { *(const u32*)&Vhs[nt * 8 + g][kf * 16 + c2],
                               *(const u32*)&Vhs[nt * 8 + g][kf * 16 + c2 + 8] };
                u32 bl2[2] = { *(const u32*)&Vls[nt * 8 + g][kf * 16 + c2],
                               *(const u32*)&Vls[nt * 8 + g][kf * 16 + c2 + 8] };
                mma16816h(o[nt], ahg[kf], bh2);
                mma16816h(o[nt], ahg[kf], bl2);
            }
        }
    }
    size_t obase = ((size_t)(b * Sc + iw + g)) * Dc + h * 64;
#pragma unroll
    for (int nt = 0; nt < 8; nt++) {
        size_t o0 = obase + nt * 8 + c2;
        size_t o1 = obase + 8 * Dc + nt * 8 + c2;
        *(u32*)(g_aoh + o0) = pkbf(o[nt][0], o[nt][1]);
        *(u32*)(g_aol + o0) = pkbf(bflo(o[nt][0]), bflo(o[nt][1]));
        *(u32*)(g_aoh + o1) = pkbf(o[nt][2], o[nt][3]);
        *(u32*)(g_aol + o1) = pkbf(bflo(o[nt][2]), bflo(o[nt][3]));
    }
}

extern "C" void kernel_launch(void* const* d_in, const int* in_sizes, int n_in,
                              void* d_out, int out_size) {
    (void)in_sizes; (void)n_in; (void)out_size;
    const float* x    = (const float*)d_in[0];
    const float* cosb = (const float*)d_in[1];
    const float* sinb = (const float*)d_in[2];
    const float* wsrc[4] = { (const float*)d_in[3], (const float*)d_in[4],
                             (const float*)d_in[5], (const float*)d_in[6] };

    float* out  = (float*)d_out;
    float* attn = out + (size_t)Mc * Dc;
    float* ent  = attn + (size_t)Mc * Hc * (size_t)Sc;

    bf16 *xh, *xl, *wh, *wl, *qh, *ql, *kh, *kl, *aoh, *aol;
    float *v;
    cudaGetSymbolAddress((void**)&xh, g_xh);   cudaGetSymbolAddress((void**)&xl, g_xl);
    cudaGetSymbolAddress((void**)&wh, g_wh);   cudaGetSymbolAddress((void**)&wl, g_wl);
    cudaGetSymbolAddress((void**)&qh, g_qh);   cudaGetSymbolAddress((void**)&ql, g_ql);
    cudaGetSymbolAddress((void**)&kh, g_kh);   cudaGetSymbolAddress((void**)&kl, g_kl);
    cudaGetSymbolAddress((void**)&aoh, g_aoh); cudaGetSymbolAddress((void**)&aol, g_aol);
    cudaGetSymbolAddress((void**)&v, g_v);

    int n4x = (int)((size_t)Mc * Dc / 4);
    int n4w = Dc * Dc / 4;
    cvt_split<<<n4x / 256, 256>>>(x, xh, xl, n4x);
    for (int i = 0; i < 4; i++)
        cvt_split<<<n4w / 256, 256>>>(wsrc[i], wh + (size_t)i * Dc * Dc, wl + (size_t)i * Dc * Dc, n4w);

    dim3 gg(Dc / 128, Mc / 128);
    gemm_bf3<<<gg, 256>>>(xh, xl, wh + 0 * (size_t)Dc * Dc, wl + 0 * (size_t)Dc * Dc,
                          qh, ql, nullptr, cosb, sinb, 0);
    gemm_bf3<<<gg, 256>>>(xh, xl, wh + 1 * (size_t)Dc * Dc, wl + 1 * (size_t)Dc * Dc,
                          kh, kl, nullptr, cosb, sinb, 0);
    gemm_bf3<<<gg, 256>>>(xh, xl, wh + 2 * (size_t)Dc * Dc, wl + 2 * (size_t)Dc * Dc,
                          nullptr, nullptr, v, cosb, sinb, 1);
    vtrans<<<dim3(Sc / 32, Dc / 32, Bc), 256>>>();
    attn1<<<dim3(Sc / 128, Bc * Hc), 256>>>(ent);
    attn2<<<dim3(Sc / 64, Bc * Hc), 128>>>(attn);
    gemm_bf3<<<gg, 256>>>(aoh, aol, wh + 3 * (size_t)Dc * Dc, wl + 3 * (size_t)Dc * Dc,
                          nullptr, nullptr, out, cosb, sinb, 1);
}

// round 9
// speedup vs baseline: 2.6781x; 1.0891x over previous
#include <cuda_runtime.h>
#include <cuda_bf16.h>
#include <cuda_fp16.h>

#define Bc 2
#define Sc 2048
#define Dc 1024
#define Hc 16
#define Mc (Bc*Sc)

typedef unsigned u32;
typedef __nv_bfloat16 bf16;

// ---------------- scratch ----------------
__device__ bf16 g_xh[(size_t)Mc*Dc], g_xl[(size_t)Mc*Dc];
__device__ bf16 g_wh[4*Dc*Dc], g_wl[4*Dc*Dc];
__device__ bf16 g_qh[(size_t)Mc*Dc], g_ql[(size_t)Mc*Dc];
__device__ bf16 g_kh[(size_t)Mc*Dc], g_kl[(size_t)Mc*Dc];
__device__ __half g_vth[(size_t)Bc*Dc*Sc], g_vtl[(size_t)Bc*Dc*Sc];
__device__ bf16 g_aoh[(size_t)Mc*Dc], g_aol[(size_t)Mc*Dc];
__device__ float g_v[(size_t)Mc*Dc];
__device__ float g_m[Mc*Hc], g_l[Mc*Hc];
__device__ __half g_wraw[(size_t)Mc*Hc*Sc];   // w' fp16, frag-native
__device__ float g_mu[(size_t)4096*512];       // per (wg, tile, row) m_used

// ---------------- helpers ----------------
__device__ __forceinline__ void mma16816(float* c, const u32* a, const u32* b) {
    asm volatile("mma.sync.aligned.m16n8k16.row.col.f32.bf16.bf16.f32 "
        "{%0,%1,%2,%3},{%4,%5,%6,%7},{%8,%9},{%0,%1,%2,%3};"
        : "+f"(c[0]), "+f"(c[1]), "+f"(c[2]), "+f"(c[3])
        : "r"(a[0]), "r"(a[1]), "r"(a[2]), "r"(a[3]), "r"(b[0]), "r"(b[1]));
}
__device__ __forceinline__ void mma16816h(float* c, const u32* a, const u32* b) {
    asm volatile("mma.sync.aligned.m16n8k16.row.col.f32.f16.f16.f32 "
        "{%0,%1,%2,%3},{%4,%5,%6,%7},{%8,%9},{%0,%1,%2,%3};"
        : "+f"(c[0]), "+f"(c[1]), "+f"(c[2]), "+f"(c[3])
        : "r"(a[0]), "r"(a[1]), "r"(a[2]), "r"(a[3]), "r"(b[0]), "r"(b[1]));
}
__device__ __forceinline__ void ldsm4(u32* r, u32 a) {
    asm volatile("ldmatrix.sync.aligned.m8n8.x4.shared.b16 {%0,%1,%2,%3}, [%4];"
        : "=r"(r[0]), "=r"(r[1]), "=r"(r[2]), "=r"(r[3]) : "r"(a));
}
__device__ __forceinline__ u32 smem_u32(const void* p) {
    return (u32)__cvta_generic_to_shared(p);
}
__device__ __forceinline__ u32 pkbf(float x, float y) {
    bf16 a = __float2bfloat16(x), b = __float2bfloat16(y);
    return (u32)__bfloat16_as_ushort(a) | ((u32)__bfloat16_as_ushort(b) << 16);
}
__device__ __forceinline__ u32 pkh(float x, float y) {
    __half2 h = __floats2half2_rn(x, y);
    return *(u32*)&h;
}
__device__ __forceinline__ float bflo(float x) {
    return x - __bfloat162float(__float2bfloat16(x));
}
__device__ __forceinline__ void cpa16(void* s, const void* g) {
    u32 ss = (u32)__cvta_generic_to_shared(s);
    asm volatile("cp.async.ca.shared.global [%0], [%1], 16;" :: "r"(ss), "l"(g));
}
__device__ __forceinline__ void cpcommit() { asm volatile("cp.async.commit_group;"); }
template<int N> __device__ __forceinline__ void cpwait() { asm volatile("cp.async.wait_group %0;" :: "n"(N)); }

// FMA-pipe exp (x <= 0), rel err ~4e-5
__device__ __forceinline__ float fexp(float x) {
    float y = fmaf(x, 1.4426950408889634f, 12582912.0f);
    float n = y - 12582912.0f;
    float f = fmaf(x, 1.4426950408889634f, -n);
    float p = 0.00961812910f;
    p = fmaf(p, f, 0.05550410866f);
    p = fmaf(p, f, 0.24022650696f);
    p = fmaf(p, f, 0.69314718056f);
    p = fmaf(p, f, 1.0f);
    return __int_as_float(__float_as_int(p) + (__float_as_int(y) << 23));
}

// ---------------- conversions ----------------
__global__ __launch_bounds__(256) void cvt_split(const float* __restrict__ in,
                                                 bf16* __restrict__ oh, bf16* __restrict__ ol, int n4) {
    int i = blockIdx.x * 256 + threadIdx.x;
    if (i >= n4) return;
    float4 v = ((const float4*)in)[i];
    ((uint2*)oh)[i] = make_uint2(pkbf(v.x, v.y), pkbf(v.z, v.w));
    ((uint2*)ol)[i] = make_uint2(pkbf(bflo(v.x), bflo(v.y)), pkbf(bflo(v.z), bflo(v.w)));
}

__global__ __launch_bounds__(256) void vtrans() {
    __shared__ float ts[32][33];
    int tx = threadIdx.x & 31, ty = threadIdx.x >> 5;
    int s0 = blockIdx.x * 32, d0 = blockIdx.y * 32, b = blockIdx.z;
#pragma unroll
    for (int i = 0; i < 4; i++)
        ts[ty + i * 8][tx] = g_v[((size_t)(b * Sc + s0 + ty + i * 8)) * Dc + d0 + tx];
    __syncthreads();
#pragma unroll
    for (int i = 0; i < 4; i++) {
        int d = ty + i * 8;
        float v = ts[tx][d];
        size_t o = ((size_t)(b * Dc + d0 + d)) * Sc + s0 + tx;
        __half vh = __float2half(v);
        g_vth[o] = vh;
        g_vtl[o] = __float2half(v - __half2float(vh));
    }
}

// ---------------- 3-term bf16 GEMM, cp.async 2-stage, LDSM frags ----------------
// mode 0: rope + bf16 hi/lo split -> Ch/Cl (Q,K).  mode 1: fp32 -> Cf (V, out)
__global__ __launch_bounds__(256) void gemm_bf3(
    const bf16* __restrict__ Ah, const bf16* __restrict__ Al,
    const bf16* __restrict__ Bh, const bf16* __restrict__ Bl,
    bf16* __restrict__ Ch, bf16* __restrict__ Cl, float* __restrict__ Cf,
    const float* __restrict__ cosb, const float* __restrict__ sinb, int mode) {
    __shared__ bf16 Ahs[2][128][24], Als[2][128][24], Bhs[2][128][24], Bls[2][128][24];
    int t = threadIdx.x, lane = t & 31, w = t >> 5;
    int wm = w & 1, wn = w >> 1;
    int g = lane >> 2, c2 = (lane & 3) * 2;
    int brow = blockIdx.y * 128, bcol = blockIdx.x * 128;
    float acc[4][4][4];
#pragma unroll
    for (int a = 0; a < 4; a++)
#pragma unroll
        for (int b2 = 0; b2 < 4; b2++)
#pragma unroll
            for (int q = 0; q < 4; q++) acc[a][b2][q] = 0.f;

    // LDSM lane addressing
    int arow = wm * 64 + ((lane >> 3) & 1) * 8 + (lane & 7);
    int acol = ((lane >> 4) & 1) * 8;
    int brw  = wn * 32 + ((lane >> 4) & 1) * 8 + (lane & 7);
    int bcl  = ((lane >> 3) & 1) * 8;

    int lr = t >> 1, lc = (t & 1) * 8;
    const bf16* pah = Ah + (size_t)(brow + lr) * Dc + lc;
    const bf16* pal = Al + (size_t)(brow + lr) * Dc + lc;
    const bf16* pbh = Bh + (size_t)(bcol + lr) * Dc + lc;
    const bf16* pbl = Bl + (size_t)(bcol + lr) * Dc + lc;

#define GLOAD(st, k0) { \
        cpa16(&Ahs[st][lr][lc], pah + (k0)); cpa16(&Als[st][lr][lc], pal + (k0)); \
        cpa16(&Bhs[st][lr][lc], pbh + (k0)); cpa16(&Bls[st][lr][lc], pbl + (k0)); }

    GLOAD(0, 0); cpcommit();
    for (int kt = 0; kt < 64; kt++) {
        if (kt < 63) { GLOAD((kt + 1) & 1, (kt + 1) * 16); cpcommit(); cpwait<1>(); }
        else cpwait<0>();
        __syncthreads();
        int st = kt & 1;
        u32 aBH = smem_u32(&Ahs[st][arow][acol]);
        u32 aBL = smem_u32(&Als[st][arow][acol]);
        u32 bBH = smem_u32(&Bhs[st][brw][bcl]);
        u32 bBL = smem_u32(&Bls[st][brw][bcl]);
        u32 a_h[4][4], a_l[4][4], b_h[2][4], b_l[2][4];
#pragma unroll
        for (int mf = 0; mf < 4; mf++) {
            ldsm4(a_h[mf], aBH + mf * 768);
            ldsm4(a_l[mf], aBL + mf * 768);
        }
#pragma unroll
        for (int nfp = 0; nfp < 2; nfp++) {
            ldsm4(b_h[nfp], bBH + nfp * 768);
            ldsm4(b_l[nfp], bBL + nfp * 768);
        }
#pragma unroll
        for (int nf = 0; nf < 4; nf++) {
            const u32* bh2 = &b_h[nf >> 1][(nf & 1) * 2];
            const u32* bl2 = &b_l[nf >> 1][(nf & 1) * 2];
#pragma unroll
            for (int mf = 0; mf < 4; mf++) {
                mma16816(acc[mf][nf], a_h[mf], bh2);
                mma16816(acc[mf][nf], a_h[mf], bl2);
                mma16816(acc[mf][nf], a_l[mf], bh2);
            }
        }
        __syncthreads();
    }
#undef GLOAD
    if (mode == 1) {
#pragma unroll
        for (int mf = 0; mf < 4; mf++)
#pragma unroll
            for (int nf = 0; nf < 4; nf++) {
                int r = brow + wm * 64 + mf * 16 + g;
                int c = bcol + wn * 32 + nf * 8 + c2;
                *(float2*)&Cf[(size_t)r * Dc + c]       = make_float2(acc[mf][nf][0], acc[mf][nf][1]);
                *(float2*)&Cf[(size_t)(r + 8) * Dc + c] = make_float2(acc[mf][nf][2], acc[mf][nf][3]);
            }
    } else {
#pragma unroll
        for (int mf = 0; mf < 4; mf++)
#pragma unroll
            for (int nf = 0; nf < 4; nf++) {
                int r = brow + wm * 64 + mf * 16 + g;
                int c = bcol + wn * 32 + nf * 8 + c2;
                int pi = (c & 63) >> 1;
                int sA = r & 2047, sB = (r + 8) & 2047;
                float csA = cosb[sA * 32 + pi], snA = sinb[sA * 32 + pi];
                float csB = cosb[sB * 32 + pi], snB = sinb[sB * 32 + pi];
                float a0 = acc[mf][nf][0], a1 = acc[mf][nf][1];
                float a2 = acc[mf][nf][2], a3 = acc[mf][nf][3];
                float o0 = a0 * csA - a1 * snA, o1 = a0 * snA + a1 * csA;
                float o2 = a2 * csB - a3 * snB, o3 = a2 * snB + a3 * csB;
                size_t off = (size_t)r * Dc + c;
                *(u32*)(Ch + off) = pkbf(o0, o1);
                *(u32*)(Cl + off) = pkbf(bflo(o0), bflo(o1));
                off = (size_t)(r + 8) * Dc + c;
                *(u32*)(Ch + off) = pkbf(o2, o3);
                *(u32*)(Cl + off) = pkbf(bflo(o2), bflo(o3));
            }
    }
}

// ---------------- pass 1: scores + softmax stats + w' + entropy ----------------
__global__ __launch_bounds__(256) void attn1(float* __restrict__ ent) {
    __shared__ bf16 Khs[2][64][72], Kls[2][64][72];
    int t = threadIdx.x, lane = t & 31, w = t >> 5;
    int g = lane >> 2, c2 = (lane & 3) * 2;
    int b = blockIdx.y >> 4, h = blockIdx.y & 15;
    int i0 = blockIdx.x * 128 + w * 16;

    const bf16* qh = g_qh + ((size_t)(b * Sc + i0 + g)) * Dc + h * 64;
    const bf16* ql = g_ql + ((size_t)(b * Sc + i0 + g)) * Dc + h * 64;
    u32 ah[4][4], al[4][4];
#pragma unroll
    for (int kf = 0; kf < 4; kf++) {
        ah[kf][0] = *(const u32*)(qh + kf * 16 + c2);
        ah[kf][1] = *(const u32*)(qh + 8 * Dc + kf * 16 + c2);
        ah[kf][2] = *(const u32*)(qh + kf * 16 + c2 + 8);
        ah[kf][3] = *(const u32*)(qh + 8 * Dc + kf * 16 + c2 + 8);
        al[kf][0] = *(const u32*)(ql + kf * 16 + c2);
        al[kf][1] = *(const u32*)(ql + 8 * Dc + kf * 16 + c2);
        al[kf][2] = *(const u32*)(ql + kf * 16 + c2 + 8);
        al[kf][3] = *(const u32*)(ql + 8 * Dc + kf * 16 + c2 + 8);
    }

    int kr = t >> 2, kc = (t & 3) * 16;
    const bf16* kgh = g_kh + ((size_t)(b * Sc + kr)) * Dc + h * 64 + kc;
    const bf16* kgl = g_kl + ((size_t)(b * Sc + kr)) * Dc + h * 64 + kc;

#define KLOAD(st, j0) { \
        cpa16(&Khs[st][kr][kc],     kgh + (size_t)(j0) * Dc); \
        cpa16(&Khs[st][kr][kc + 8], kgh + (size_t)(j0) * Dc + 8); \
        cpa16(&Kls[st][kr][kc],     kgl + (size_t)(j0) * Dc); \
        cpa16(&Kls[st][kr][kc + 8], kgl + (size_t)(j0) * Dc + 8); }

    // LDSM lane addressing for K (B operand)
    int krow = ((lane >> 4) & 1) * 8 + (lane & 7);
    int kcol = ((lane >> 3) & 1) * 8;

    float m0 = -1e30f, m1 = -1e30f, l0 = 0.f, l1 = 0.f, ws0 = 0.f, ws1 = 0.f;
    size_t wg = ((size_t)blockIdx.y * 16 + blockIdx.x) * 8 + w;
    uint2* wout = (uint2*)g_wraw + wg * 8192;
    float* muout = g_mu + wg * 512;

    KLOAD(0, 0); cpcommit();
    for (int jt = 0; jt < 32; jt++) {
        int j0 = jt * 64;
        if (jt < 31) { KLOAD((jt + 1) & 1, j0 + 64); cpcommit(); cpwait<1>(); }
        else cpwait<0>();
        __syncthreads();
        int st = jt & 1;
        u32 kBH = smem_u32(&Khs[st][krow][kcol]);
        u32 kBL = smem_u32(&Kls[st][krow][kcol]);
        float sc[8][4];
#pragma unroll
        for (int nt = 0; nt < 8; nt++) { sc[nt][0] = sc[nt][1] = sc[nt][2] = sc[nt][3] = 0.f; }
#pragma unroll
        for (int ntp = 0; ntp < 4; ntp++) {
#pragma unroll
            for (int kf = 0; kf < 4; kf++) {
                u32 off = (u32)(ntp * 16 * 144 + kf * 32);
                u32 bh4[4], bl4[4];
                ldsm4(bh4, kBH + off);
                ldsm4(bl4, kBL + off);
                mma16816(sc[2 * ntp],     ah[kf], &bh4[0]);
                mma16816(sc[2 * ntp],     ah[kf], &bl4[0]);
                mma16816(sc[2 * ntp],     al[kf], &bh4[0]);
                mma16816(sc[2 * ntp + 1], ah[kf], &bh4[2]);
                mma16816(sc[2 * ntp + 1], ah[kf], &bl4[2]);
                mma16816(sc[2 * ntp + 1], al[kf], &bh4[2]);
            }
        }
#pragma unroll
        for (int nt = 0; nt < 8; nt++) {
            sc[nt][0] *= 0.125f; sc[nt][1] *= 0.125f; sc[nt][2] *= 0.125f; sc[nt][3] *= 0.125f;
        }
        __syncthreads();
        float tm0 = -1e30f, tm1 = -1e30f;
#pragma unroll
        for (int nt = 0; nt < 8; nt++) {
            tm0 = fmaxf(tm0, fmaxf(sc[nt][0], sc[nt][1]));
            tm1 = fmaxf(tm1, fmaxf(sc[nt][2], sc[nt][3]));
        }
        tm0 = fmaxf(tm0, __shfl_xor_sync(~0u, tm0, 1));
        tm0 = fmaxf(tm0, __shfl_xor_sync(~0u, tm0, 2));
        tm1 = fmaxf(tm1, __shfl_xor_sync(~0u, tm1, 1));
        tm1 = fmaxf(tm1, __shfl_xor_sync(~0u, tm1, 2));
        float mn0 = fmaxf(m0, tm0), mn1 = fmaxf(m1, tm1);
        float cr0 = __expf(m0 - mn0), cr1 = __expf(m1 - mn1);
        l0 *= cr0; ws0 *= cr0; l1 *= cr1; ws1 *= cr1;
#pragma unroll
        for (int nt = 0; nt < 8; nt++) {
            float e0 = fexp(sc[nt][0] - mn0), e1 = fexp(sc[nt][1] - mn0);     // FMA pipe
            float e2 = __expf(sc[nt][2] - mn1), e3 = __expf(sc[nt][3] - mn1); // MUFU pipe
            l0 += e0 + e1;
            ws0 = fmaf(e0, sc[nt][0], fmaf(e1, sc[nt][1], ws0));
            l1 += e2 + e3;
            ws1 = fmaf(e2, sc[nt][2], fmaf(e3, sc[nt][3], ws1));
            __half2 p01 = __floats2half2_rn(e0, e1);
            __half2 p23 = __floats2half2_rn(e2, e3);
            wout[(size_t)(j0 / 8 + nt) * 32 + lane] = make_uint2(*(u32*)&p01, *(u32*)&p23);
        }
        m0 = mn0; m1 = mn1;
        if ((lane & 3) == 0) {
            muout[jt * 16 + g * 2]     = mn0;
            muout[jt * 16 + g * 2 + 1] = mn1;
        }
    }
#undef KLOAD
#pragma unroll
    for (int o = 1; o < 4; o <<= 1) {
        float om = __shfl_xor_sync(~0u, m0, o), ol = __shfl_xor_sync(~0u, l0, o),
              ow = __shfl_xor_sync(~0u, ws0, o);
        float mn = fmaxf(m0, om), ca = __expf(m0 - mn), cb = __expf(om - mn);
        l0 = l0 * ca + ol * cb; ws0 = ws0 * ca + ow * cb; m0 = mn;
        om = __shfl_xor_sync(~0u, m1, o); ol = __shfl_xor_sync(~0u, l1, o);
        ow = __shfl_xor_sync(~0u, ws1, o);
        mn = fmaxf(m1, om); ca = __expf(m1 - mn); cb = __expf(om - mn);
        l1 = l1 * ca + ol * cb; ws1 = ws1 * ca + ow * cb; m1 = mn;
    }
    if ((lane & 3) == 0) {
        int idx0 = (b * Sc + i0 + g) * Hc + h;
        g_m[idx0] = m0; g_l[idx0] = l0;
        g_m[idx0 + 8 * Hc] = m1; g_l[idx0 + 8 * Hc] = l1;
        ent[idx0]          = __log2f(l0) + (m0 - ws0 / l0) * 1.4426950408889634f;
        ent[idx0 + 8 * Hc] = __log2f(l1) + (m1 - ws1 / l1) * 1.4426950408889634f;
    }
}

// ---------------- pass 2: w = w'*corr -> out, AV fp16 2-term, bf16 split o ----------------
__global__ __launch_bounds__(128) void attn2(float* __restrict__ attnw) {
    __shared__ __half Vhs[64][72], Vls[64][72];
    __shared__ float Ws[64][68];
    int t = threadIdx.x, lane = t & 31, w = t >> 5;
    int g = lane >> 2, c2 = (lane & 3) * 2;
    int b = blockIdx.y >> 4, h = blockIdx.y & 15;
    int ib = blockIdx.x;
    int i0 = ib * 64;
    int iw = i0 + w * 16;
    size_t wg = ((size_t)blockIdx.y * 16 + (ib >> 1)) * 8 + (ib & 1) * 4 + w;
    const uint2* win = (const uint2*)g_wraw + wg * 8192;
    const float* muin = g_mu + wg * 512;
    int idx0 = (b * Sc + iw + g) * Hc + h;
    float m0 = g_m[idx0], li0 = 1.f / g_l[idx0];
    float m1 = g_m[idx0 + 8 * Hc], li1 = 1.f / g_l[idx0 + 8 * Hc];

    int vr = t >> 1, vc = (t & 1) * 32;
    const __half* vgh = g_vth + ((size_t)(b * Dc + h * 64 + vr)) * Sc + vc;
    const __half* vgl = g_vtl + ((size_t)(b * Dc + h * 64 + vr)) * Sc + vc;

    // LDSM lane addressing for V (B operand)
    int vrow = ((lane >> 4) & 1) * 8 + (lane & 7);
    int vcol = ((lane >> 3) & 1) * 8;

    float o[8][4];
#pragma unroll
    for (int n = 0; n < 8; n++)
#pragma unroll
        for (int q = 0; q < 4; q++) o[n][q] = 0.f;

    for (int jt = 0; jt < 32; jt++) {
        int j0 = jt * 64;
        __syncthreads();
#pragma unroll
        for (int c = 0; c < 32; c += 8) {
            cpa16(&Vhs[vr][vc + c], vgh + j0 + c);
            cpa16(&Vls[vr][vc + c], vgl + j0 + c);
        }
        cpcommit();

        float cc0 = __expf(muin[jt * 16 + g * 2]     - m0) * li0;
        float cc1 = __expf(muin[jt * 16 + g * 2 + 1] - m1) * li1;

        float wv[8][4];
#pragma unroll
        for (int ff = 0; ff < 8; ff++) {
            uint2 pw = win[(size_t)(j0 / 8 + ff) * 32 + lane];
            float2 p01 = __half22float2(*(__half2*)&pw.x);
            float2 p23 = __half22float2(*(__half2*)&pw.y);
            wv[ff][0] = p01.x * cc0; wv[ff][1] = p01.y * cc0;
            wv[ff][2] = p23.x * cc1; wv[ff][3] = p23.y * cc1;
            int ro = w * 16 + g;
            Ws[ro][ff * 8 + c2]         = wv[ff][0];
            Ws[ro][ff * 8 + c2 + 1]     = wv[ff][1];
            Ws[ro + 8][ff * 8 + c2]     = wv[ff][2];
            Ws[ro + 8][ff * 8 + c2 + 1] = wv[ff][3];
        }
        u32 ahg[4][4];
#pragma unroll
        for (int kf = 0; kf < 4; kf++) {
            ahg[kf][0] = pkh(wv[2*kf][0], wv[2*kf][1]);
            ahg[kf][1] = pkh(wv[2*kf][2], wv[2*kf][3]);
            ahg[kf][2] = pkh(wv[2*kf+1][0], wv[2*kf+1][1]);
            ahg[kf][3] = pkh(wv[2*kf+1][2], wv[2*kf+1][3]);
        }
        cpwait<0>();
        __syncthreads();
#pragma unroll
        for (int r8 = 0; r8 < 8; r8++) {
            int id = t + r8 * 128;
            int row = id >> 4, c4 = (id & 15) * 4;
            *(float4*)(attnw + ((size_t)((b * Sc + i0 + row) * Hc + h)) * Sc + j0 + c4) =
                *(float4*)&Ws[row][c4];
        }
        u32 vBH = smem_u32(&Vhs[vrow][vcol]);
        u32 vBL = smem_u32(&Vls[vrow][vcol]);
#pragma unroll
        for (int ntp = 0; ntp < 4; ntp++) {
#pragma unroll
            for (int kf = 0; kf < 4; kf++) {
                u32 off = (u32)(ntp * 16 * 144 + kf * 32);
                u32 vh4[4], vl4[4];
                ldsm4(vh4, vBH + off);
                ldsm4(vl4, vBL + off);
                mma16816h(o[2 * ntp],     ahg[kf], &vh4[0]);
                mma16816h(o[2 * ntp],     ahg[kf], &vl4[0]);
                mma16816h(o[2 * ntp + 1], ahg[kf], &vh4[2]);
                mma16816h(o[2 * ntp + 1], ahg[kf], &vl4[2]);
            }
        }
    }
    size_t obase = ((size_t)(b * Sc + iw + g)) * Dc + h * 64;
#pragma unroll
    for (int nt = 0; nt < 8; nt++) {
        size_t o0 = obase + nt * 8 + c2;
        size_t o1 = obase + 8 * Dc + nt * 8 + c2;
        *(u32*)(g_aoh + o0) = pkbf(o[nt][0], o[nt][1]);
        *(u32*)(g_aol + o0) = pkbf(bflo(o[nt][0]), bflo(o[nt][1]));
        *(u32*)(g_aoh + o1) = pkbf(o[nt][2], o[nt][3]);
        *(u32*)(g_aol + o1) = pkbf(bflo(o[nt][2]), bflo(o[nt][3]));
    }
}

extern "C" void kernel_launch(void* const* d_in, const int* in_sizes, int n_in,
                              void* d_out, int out_size) {
    (void)in_sizes; (void)n_in; (void)out_size;
    const float* x    = (const float*)d_in[0];
    const float* cosb = (const float*)d_in[1];
    const float* sinb = (const float*)d_in[2];
    const float* wsrc[4] = { (const float*)d_in[3], (const float*)d_in[4],
                             (const float*)d_in[5], (const float*)d_in[6] };

    float* out  = (float*)d_out;
    float* attn = out + (size_t)Mc * Dc;
    float* ent  = attn + (size_t)Mc * Hc * (size_t)Sc;

    bf16 *xh, *xl, *wh, *wl, *qh, *ql, *kh, *kl, *aoh, *aol;
    float *v;
    cudaGetSymbolAddress((void**)&xh, g_xh);   cudaGetSymbolAddress((void**)&xl, g_xl);
    cudaGetSymbolAddress((void**)&wh, g_wh);   cudaGetSymbolAddress((void**)&wl, g_wl);
    cudaGetSymbolAddress((void**)&qh, g_qh);   cudaGetSymbolAddress((void**)&ql, g_ql);
    cudaGetSymbolAddress((void**)&kh, g_kh);   cudaGetSymbolAddress((void**)&kl, g_kl);
    cudaGetSymbolAddress((void**)&aoh, g_aoh); cudaGetSymbolAddress((void**)&aol, g_aol);
    cudaGetSymbolAddress((void**)&v, g_v);

    int n4x = (int)((size_t)Mc * Dc / 4);
    int n4w = Dc * Dc / 4;
    cvt_split<<<n4x / 256, 256>>>(x, xh, xl, n4x);
    for (int i = 0; i < 4; i++)
        cvt_split<<<n4w / 256, 256>>>(wsrc[i], wh + (size_t)i * Dc * Dc, wl + (size_t)i * Dc * Dc, n4w);

    dim3 gg(Dc / 128, Mc / 128);
    gemm_bf3<<<gg, 256>>>(xh, xl, wh + 0 * (size_t)Dc * Dc, wl + 0 * (size_t)Dc * Dc,
                          qh, ql, nullptr, cosb, sinb, 0);
    gemm_bf3<<<gg, 256>>>(xh, xl, wh + 1 * (size_t)Dc * Dc, wl + 1 * (size_t)Dc * Dc,
                          kh, kl, nullptr, cosb, sinb, 0);
    gemm_bf3<<<gg, 256>>>(xh, xl, wh + 2 * (size_t)Dc * Dc, wl + 2 * (size_t)Dc * Dc,
                          nullptr, nullptr, v, cosb, sinb, 1);
    vtrans<<<dim3(Sc / 32, Dc / 32, Bc), 256>>>();
    attn1<<<dim3(Sc / 128, Bc * Hc), 256>>>(ent);
    attn2<<<dim3(Sc / 64, Bc * Hc), 128>>>(attn);
    gemm_bf3<<<gg, 256>>>(aoh, aol, wh + 3 * (size_t)Dc * Dc, wl + 3 * (size_t)Dc * Dc,
                          nullptr, nullptr, out, cosb, sinb, 1);
}